// round 1
// baseline (speedup 1.0000x reference)
#include <cuda_runtime.h>
#include <math.h>

#define NB   128   // batch
#define NC   64    // channels
#define NH   64
#define NW   64
#define NPIX (NH*NW)
#define KK   49

// ---------------- scratch (device globals; no allocations allowed) ----------
__device__ float g_rubinw[NB*NPIX*NC];          // rubin_n * swraw, pixel-major [b][pix][c]
__device__ float g_visn  [NB*NPIX*NC];          // vis_n,            pixel-major [b][pix][c]
__device__ float g_costpart[NB*8*KK];           // per (b, row-tile) partial costs
__device__ float g_poolr[NB*NH*NC];             // per (b,h) partial pools
__device__ float g_poolv[NB*NH*NC];
__device__ float g_Spart[NB*NH];                // per (b,h) partial sum of swraw

// =========================== Kernel A =======================================
// Per (b, row h): 1x1-conv projections, L2-normalize, energy, sw, pools.
// 256 threads: tx = pixel col (0..63), ty = 16-wide output chunk (0..3).
__global__ void __launch_bounds__(256)
kA(const float* __restrict__ rubin, const float* __restrict__ vis,
   const float* __restrict__ wr, const float* __restrict__ wv, float inv_gsum)
{
    const int h = blockIdx.x, b = blockIdx.y;
    const int tid = threadIdx.x, tx = tid & 63, ty = tid >> 6;

    __shared__ float sWr[64*68];   // transposed [c][o], stride 68 (16B aligned, low conflict)
    __shared__ float sWv[64*68];
    __shared__ float sxr[8*64];
    __shared__ float sxv[8*64];
    __shared__ float ssqr[4][64];
    __shared__ float ssqv[4][64];
    __shared__ float spr[64][2];
    __shared__ float spv[64][2];
    __shared__ float sSh[2];

    for (int idx = tid; idx < 4096; idx += 256) {
        int o = idx >> 6, c = idx & 63;            // global read coalesced over c
        sWr[c*68 + o] = wr[idx];
        sWv[c*68 + o] = wv[idx];
    }

    const float yy = -1.f + 2.f * (float)h  / 63.f;
    const float xx = -1.f + 2.f * (float)tx / 63.f;
    const float g  = expf(-2.f * (yy*yy + xx*xx)) * inv_gsum;   // normalized gauss

    float4 ar[4], av[4];
#pragma unroll
    for (int j = 0; j < 4; j++) { ar[j] = make_float4(0,0,0,0); av[j] = make_float4(0,0,0,0); }

    const int base_in = b*NC*NPIX + h*64;          // x[b][c][h][w] = base + c*4096 + w

    for (int c0 = 0; c0 < 64; c0 += 8) {
        __syncthreads();
#pragma unroll
        for (int k2 = 0; k2 < 2; k2++) {
            int idx = tid + k2*256;
            int i = idx >> 6, px = idx & 63;
            int ga = base_in + (c0 + i)*NPIX + px;
            sxr[idx] = rubin[ga];
            sxv[idx] = vis[ga];
        }
        __syncthreads();
#pragma unroll
        for (int i = 0; i < 8; i++) {
            const int c = c0 + i;
            const float xr = sxr[i*64 + tx];
            const float xv = sxv[i*64 + tx];
            const float4* wr4 = (const float4*)(sWr + c*68 + ty*16);  // broadcast loads
            const float4* wv4 = (const float4*)(sWv + c*68 + ty*16);
#pragma unroll
            for (int j = 0; j < 4; j++) {
                float4 w4 = wr4[j];
                ar[j].x = fmaf(w4.x, xr, ar[j].x);
                ar[j].y = fmaf(w4.y, xr, ar[j].y);
                ar[j].z = fmaf(w4.z, xr, ar[j].z);
                ar[j].w = fmaf(w4.w, xr, ar[j].w);
                float4 v4 = wv4[j];
                av[j].x = fmaf(v4.x, xv, av[j].x);
                av[j].y = fmaf(v4.y, xv, av[j].y);
                av[j].z = fmaf(v4.z, xv, av[j].z);
                av[j].w = fmaf(v4.w, xv, av[j].w);
            }
        }
        // pools: Sum_px raw_x[c][px]*g ; c = c0 + ty + 4*rep, reduced per warp-half
#pragma unroll
        for (int rep = 0; rep < 2; rep++) {
            int i = ty + rep*4;
            float vr = sxr[i*64 + tx] * g;
            float vv = sxv[i*64 + tx] * g;
#pragma unroll
            for (int off = 16; off > 0; off >>= 1) {
                vr += __shfl_down_sync(0xffffffffu, vr, off);
                vv += __shfl_down_sync(0xffffffffu, vv, off);
            }
            if ((tx & 31) == 0) {
                spr[c0 + i][tx >> 5] = vr;
                spv[c0 + i][tx >> 5] = vv;
            }
        }
    }

    float sqr = 0.f, sqv = 0.f;
#pragma unroll
    for (int j = 0; j < 4; j++) {
        sqr += ar[j].x*ar[j].x + ar[j].y*ar[j].y + ar[j].z*ar[j].z + ar[j].w*ar[j].w;
        sqv += av[j].x*av[j].x + av[j].y*av[j].y + av[j].z*av[j].z + av[j].w*av[j].w;
    }
    ssqr[ty][tx] = sqr; ssqv[ty][tx] = sqv;
    __syncthreads();
    const float ssr = ssqr[0][tx] + ssqr[1][tx] + ssqr[2][tx] + ssqr[3][tx];
    const float ssv = ssqv[0][tx] + ssqv[1][tx] + ssqv[2][tx] + ssqv[3][tx];
    const float sr = 1.f / fmaxf(sqrtf(ssr), 1e-6f);
    const float sv = 1.f / fmaxf(sqrtf(ssv), 1e-6f);
    const float e  = ssr * sr * sr;           // energy (==1 unless degenerate)
    const float swraw = e * g;
    const float fr = sr * swraw;              // fold sw into rubin

    float4* outr = (float4*)(g_rubinw + ((size_t)(b*NPIX + h*64 + tx))*NC + ty*16);
    float4* outv = (float4*)(g_visn   + ((size_t)(b*NPIX + h*64 + tx))*NC + ty*16);
#pragma unroll
    for (int j = 0; j < 4; j++) {
        float4 t = ar[j]; t.x *= fr; t.y *= fr; t.z *= fr; t.w *= fr; outr[j] = t;
        float4 u = av[j]; u.x *= sv; u.y *= sv; u.z *= sv; u.w *= sv; outv[j] = u;
    }
    if (ty == 0) {
        float s = swraw;
#pragma unroll
        for (int off = 16; off > 0; off >>= 1) s += __shfl_down_sync(0xffffffffu, s, off);
        if ((tx & 31) == 0) sSh[tx >> 5] = s;
    }
    __syncthreads();
    if (tid < 64) {
        g_poolr[(b*NH + h)*NC + tid] = spr[tid][0] + spr[tid][1];
        g_poolv[(b*NH + h)*NC + tid] = spv[tid][0] + spv[tid][1];
    }
    if (tid == 0) g_Spart[b*NH + h] = sSh[0] + sSh[1];
}

// =========================== Kernel B =======================================
// Correlation costs. Block = (b, 8-row tile). 128 threads; each owns 4 adjacent
// columns (row = tid&7, cg = tid>>3). Sliding register window over dx.
// Dynamic smem: vis tile [4 cc4][14 rows][65 cols] float4  = 58240 B.
__global__ void __launch_bounds__(128, 3)
kB()
{
    const int tile = blockIdx.x;            // 0..7
    const int b    = blockIdx.y;
    const int h0   = tile * 8;
    const int tid  = threadIdx.x;
    const int row  = tid & 7;
    const int cg   = tid >> 3;              // 0..15, columns 4cg..4cg+3

    extern __shared__ float4 sv[];          // [(cc4*14 + r)*65 + col]

    float acc[KK];
#pragma unroll
    for (int k = 0; k < KK; k++) acc[k] = 0.f;

    for (int c0 = 0; c0 < 64; c0 += 16) {
        __syncthreads();
        for (int idx = tid; idx < 14*64*4; idx += 128) {
            int cc4 = idx & 3, col = (idx >> 2) & 63, r = idx >> 8;
            int gr = min(max(h0 + r - 3, 0), 63);
            sv[(cc4*14 + r)*65 + col] =
                *(const float4*)(g_visn + ((size_t)(b*NPIX + gr*64 + col))*NC + c0 + cc4*4);
        }
        __syncthreads();

        for (int cc4 = 0; cc4 < 4; cc4++) {
            float4 rb[4];
#pragma unroll
            for (int p = 0; p < 4; p++)
                rb[p] = *(const float4*)(g_rubinw +
                        ((size_t)(b*NPIX + (h0 + row)*64 + cg*4 + p))*NC + c0 + cc4*4);
#pragma unroll
            for (int dy = 0; dy < 7; dy++) {
                const float4* base = &sv[(cc4*14 + row + dy)*65];
                float4 w[10];
#pragma unroll
                for (int j = 0; j < 10; j++) {
                    int col = min(max(cg*4 + j - 3, 0), 63);
                    w[j] = base[col];
                }
#pragma unroll
                for (int dx = 0; dx < 7; dx++) {
#pragma unroll
                    for (int p = 0; p < 4; p++) {
                        float4 ww = w[p + dx];
                        float s = acc[dy*7 + dx];
                        s = fmaf(rb[p].x, ww.x, s);
                        s = fmaf(rb[p].y, ww.y, s);
                        s = fmaf(rb[p].z, ww.z, s);
                        s = fmaf(rb[p].w, ww.w, s);
                        acc[dy*7 + dx] = s;
                    }
                }
            }
        }
    }

    __shared__ float sred[4][KK];
    const int wid = tid >> 5, lane = tid & 31;
#pragma unroll
    for (int k = 0; k < KK; k++) {
        float v = acc[k];
#pragma unroll
        for (int off = 16; off > 0; off >>= 1) v += __shfl_down_sync(0xffffffffu, v, off);
        if (lane == 0) sred[wid][k] = v;
    }
    __syncthreads();
    if (tid < KK)
        g_costpart[(b*8 + tile)*KK + tid] =
            sred[0][tid] + sred[1][tid] + sred[2][tid] + sred[3][tid];
}

// =========================== Kernel C =======================================
__device__ __forceinline__ float gelu_exact(float x) {
    return 0.5f * x * (1.f + erff(x * 0.70710678118654752440f));
}

__global__ void __launch_bounds__(128)
kC(const float* __restrict__ p2s, const int* __restrict__ band_idx,
   const float* __restrict__ log_temp, const float* __restrict__ band_emb,
   const float* __restrict__ w1, const float* __restrict__ b1,
   const float* __restrict__ w2, const float* __restrict__ b2,
   const float* __restrict__ w3, const float* __restrict__ b3,
   float* __restrict__ out, int stride)
{
    const int b = blockIdx.x, tid = threadIdx.x;
    __shared__ float sfeat[212];
    __shared__ float scost[KK];
    __shared__ float sh1[128], sh2[128], sout3[3];
    __shared__ float sS, scdx, scdy, sconf;

    // deterministic partial reductions
    if (tid == 0) {
        float s = 0.f;
        for (int h = 0; h < NH; h++) s += g_Spart[b*NH + h];
        sS = s;
    }
    if (tid < KK) {
        float c = 0.f;
        for (int t = 0; t < 8; t++) c += g_costpart[(b*8 + t)*KK + tid];
        scost[tid] = c;
    }
    if (tid < 64) {
        float pr = 0.f, pv = 0.f;
        for (int h = 0; h < NH; h++) {
            pr += g_poolr[(b*NH + h)*NC + tid];
            pv += g_poolv[(b*NH + h)*NC + tid];
        }
        sfeat[tid] = pr; sfeat[64 + tid] = pv; sfeat[128 + tid] = pr - pv;
    }
    __syncthreads();

    if (tid == 0) {
        const float temp  = fmaxf(expf(log_temp[0]), 1e-3f);
        const float scale = 1.f / ((sS + 1e-8f) * 8.f * temp);  // sqrt(C)=8
        float l[KK], mx = -1e30f;
        for (int k = 0; k < KK; k++) { l[k] = scost[k] * scale; mx = fmaxf(mx, l[k]); }
        float sum = 0.f;
        for (int k = 0; k < KK; k++) { float p = expf(l[k] - mx); l[k] = p; sum += p; }
        const float inv = 1.f / sum;
        float cdx = 0.f, cdy = 0.f, cf = 0.f;
        for (int k = 0; k < KK; k++) {
            float p = l[k] * inv;
            cf  = fmaxf(cf, p);
            cdx += p * (float)((k % 7) - 3);
            cdy += p * (float)((k / 7) - 3);
        }
        scdx = cdx; scdy = cdy; sconf = cf;
        sfeat[192] = cdx; sfeat[193] = cdy;
    }
    if (tid < 16) sfeat[194 + tid] = band_emb[band_idx[b]*16 + tid];
    __syncthreads();

    float a = b1[tid];
    for (int f = 0; f < 210; f++) a = fmaf(sfeat[f], w1[f*128 + tid], a);
    sh1[tid] = gelu_exact(a);
    __syncthreads();

    a = b2[tid];
    for (int f = 0; f < 128; f++) a = fmaf(sh1[f], w2[f*128 + tid], a);
    sh2[tid] = gelu_exact(a);
    __syncthreads();

    if (tid < 3) {
        float a3 = b3[tid];
        for (int f = 0; f < 128; f++) a3 = fmaf(sh2[f], w3[f*3 + tid], a3);
        sout3[tid] = a3;
    }
    __syncthreads();

    if (tid == 0) {
        const float dx = scdx + sout3[0];
        const float dy = scdy + sout3[1];
        const float ls = fminf(fmaxf(sout3[2], -6.f), 3.f);
        const float s0 = p2s[b*4 + 0]*dx + p2s[b*4 + 1]*dy;
        const float s1 = p2s[b*4 + 2]*dx + p2s[b*4 + 3]*dy;
        float* o = out + (size_t)b * stride;
        if (stride > 0) o[0] = dx;
        if (stride > 1) o[1] = dy;
        if (stride > 2) o[2] = s0;
        if (stride > 3) o[3] = s1;
        if (stride > 4) o[4] = ls;
        if (stride > 5) o[5] = sconf;
        for (int j = 6; j < stride; j++) o[j] = 0.f;
    }
}

// =========================== launch =========================================
extern "C" void kernel_launch(void* const* d_in, const int* in_sizes, int n_in,
                              void* d_out, int out_size)
{
    const float* rubin = (const float*)d_in[0];
    const float* vis   = (const float*)d_in[1];
    const float* p2s   = (const float*)d_in[2];
    const int*   bidx  = (const int*)  d_in[3];
    const float* wr    = (const float*)d_in[4];
    const float* wv    = (const float*)d_in[5];
    const float* lt    = (const float*)d_in[6];
    const float* bemb  = (const float*)d_in[7];
    const float* w1    = (const float*)d_in[8];
    const float* b1    = (const float*)d_in[9];
    const float* w2    = (const float*)d_in[10];
    const float* b2    = (const float*)d_in[11];
    const float* w3    = (const float*)d_in[12];
    const float* b3    = (const float*)d_in[13];
    float* out = (float*)d_out;
    const int stride = out_size / NB;

    // gauss normalizer (separable, H=W=64)
    double Sy = 0.0;
    for (int i = 0; i < 64; i++) {
        double y = -1.0 + 2.0 * (double)i / 63.0;
        Sy += exp(-2.0 * y * y);
    }
    const float inv_gsum = (float)(1.0 / (Sy * Sy));

    const int kb_smem = 4 * 14 * 65 * 16;   // 58240 B
    cudaFuncSetAttribute(kB, cudaFuncAttributeMaxDynamicSharedMemorySize, kb_smem);

    kA<<<dim3(NH, NB), 256>>>(rubin, vis, wr, wv, inv_gsum);
    kB<<<dim3(8, NB), 128, kb_smem>>>();
    kC<<<NB, 128>>>(p2s, bidx, lt, bemb, w1, b1, w2, b2, w3, b3, out, stride);
}

// round 2
// speedup vs baseline: 1.3760x; 1.3760x over previous
#include <cuda_runtime.h>
#include <math.h>

#define NB   128   // batch
#define NC   64    // channels
#define NH   64
#define NW   64
#define NPIX (NH*NW)
#define KK   49

// ---------------- scratch (device globals; no allocations allowed) ----------
__device__ float g_rubinw[NB*NPIX*NC];          // rubin_n * swraw, pixel-major [b][pix][c]
__device__ float g_visn  [NB*NPIX*NC];          // vis_n,            pixel-major [b][pix][c]
__device__ float g_costpart[NB*8*KK];           // per (b, row-tile) partial costs
__device__ float g_poolr[NB*NH*NC];             // per (b,h) partial pools
__device__ float g_poolv[NB*NH*NC];
__device__ float g_Spart[NB*NH];                // per (b,h) partial sum of swraw

// =========================== Kernel A =======================================
// One block per (b, row h). 256 threads, 8 warps.
// Register tile: each thread owns 2 pixels (lane, lane+32) x 8 outputs (warp
// owns outputs 8*wid..8*wid+7) for both tensors -> 32 accumulators.
// x is staged TRANSPOSED in smem [pix][c] (stride 68) so a float4 spans 4
// channels; weight rows w[o][c] are read as warp-broadcast float4s.
// Dynamic smem layout (floats):
#define OFF_WR  0
#define OFF_WV  4352
#define OFF_XR  8704
#define OFF_XV  13056
#define OFF_SQR 17408
#define OFF_SQV 17920
#define OFF_PR  18432
#define OFF_PV  18688
#define OFF_GX  18944
#define OFF_FR  19008
#define OFF_SV  19072
#define OFF_SW  19136
#define KA_SMEM_FLOATS 19200

__global__ void __launch_bounds__(256, 2)
kA(const float* __restrict__ rubin, const float* __restrict__ vis,
   const float* __restrict__ wr, const float* __restrict__ wv, float inv_gsum)
{
    extern __shared__ float sm[];
    float* sWr = sm + OFF_WR;    // [o][c], stride 68
    float* sWv = sm + OFF_WV;
    float* sXr = sm + OFF_XR;    // [pix][c], stride 68
    float* sXv = sm + OFF_XV;
    float* sSQR = sm + OFF_SQR;  // [8][64]
    float* sSQV = sm + OFF_SQV;
    float* sPr = sm + OFF_PR;    // [4][64]
    float* sPv = sm + OFF_PV;
    float* sGx = sm + OFF_GX;    // [64]
    float* sFr = sm + OFF_FR;    // [64]
    float* sSv = sm + OFF_SV;    // [64]
    float* sSw = sm + OFF_SW;    // [64]

    const int h = blockIdx.x, b = blockIdx.y;
    const int tid = threadIdx.x;
    const int wid = tid >> 5, lane = tid & 31;

    // ---- load weights (w[o][c] row-major already matches needed layout) ----
    for (int idx = tid; idx < 4096; idx += 256) {
        int o = idx >> 6, c = idx & 63;
        sWr[o*68 + c] = wr[idx];
        sWv[o*68 + c] = wv[idx];
    }
    if (tid < 64) {
        float xxg = -1.f + 2.f * (float)tid / 63.f;
        sGx[tid] = expf(-2.f * xxg * xxg);
    }

    // ---- stage x transposed: sX[pix][c] ----
    {
        const int w0 = tid & 63, cq = tid >> 6;   // cq = channel quarter-of-16
        const size_t rowbase = (size_t)b*NC*NPIX + (size_t)h*64 + w0;
#pragma unroll
        for (int it = 0; it < 4; it++) {
            int c0 = cq*4 + it*16;
            float4 vr, vv;
            vr.x = rubin[rowbase + (size_t)(c0+0)*NPIX];
            vr.y = rubin[rowbase + (size_t)(c0+1)*NPIX];
            vr.z = rubin[rowbase + (size_t)(c0+2)*NPIX];
            vr.w = rubin[rowbase + (size_t)(c0+3)*NPIX];
            vv.x = vis  [rowbase + (size_t)(c0+0)*NPIX];
            vv.y = vis  [rowbase + (size_t)(c0+1)*NPIX];
            vv.z = vis  [rowbase + (size_t)(c0+2)*NPIX];
            vv.w = vis  [rowbase + (size_t)(c0+3)*NPIX];
            *(float4*)&sXr[w0*68 + c0] = vr;
            *(float4*)&sXv[w0*68 + c0] = vv;
        }
    }
    __syncthreads();

    // ---- register-tiled GEMM ----
    const int og = wid * 8;
    const int p0 = lane, p1 = lane + 32;
    float accr[2][8], accv[2][8];
#pragma unroll
    for (int o = 0; o < 8; o++) { accr[0][o]=0.f; accr[1][o]=0.f; accv[0][o]=0.f; accv[1][o]=0.f; }

#pragma unroll 4
    for (int c0 = 0; c0 < 64; c0 += 4) {
        const float4 x0r = *(const float4*)&sXr[p0*68 + c0];
        const float4 x1r = *(const float4*)&sXr[p1*68 + c0];
        const float4 x0v = *(const float4*)&sXv[p0*68 + c0];
        const float4 x1v = *(const float4*)&sXv[p1*68 + c0];
#pragma unroll
        for (int o = 0; o < 8; o++) {
            const float4 w4 = *(const float4*)&sWr[(og+o)*68 + c0];
            accr[0][o] = fmaf(w4.x,x0r.x, fmaf(w4.y,x0r.y, fmaf(w4.z,x0r.z, fmaf(w4.w,x0r.w, accr[0][o]))));
            accr[1][o] = fmaf(w4.x,x1r.x, fmaf(w4.y,x1r.y, fmaf(w4.z,x1r.z, fmaf(w4.w,x1r.w, accr[1][o]))));
            const float4 v4 = *(const float4*)&sWv[(og+o)*68 + c0];
            accv[0][o] = fmaf(v4.x,x0v.x, fmaf(v4.y,x0v.y, fmaf(v4.z,x0v.z, fmaf(v4.w,x0v.w, accv[0][o]))));
            accv[1][o] = fmaf(v4.x,x1v.x, fmaf(v4.y,x1v.y, fmaf(v4.z,x1v.z, fmaf(v4.w,x1v.w, accv[1][o]))));
        }
    }

    // ---- pool partials over raw x (still resident in sX) ----
    {
        const int c = tid & 63, q = tid >> 6;
        float pr = 0.f, pv = 0.f;
#pragma unroll
        for (int w = 0; w < 16; w++) {
            const int px = q*16 + w;
            const float gxw = sGx[px];
            pr = fmaf(sXr[px*68 + c], gxw, pr);
            pv = fmaf(sXv[px*68 + c], gxw, pv);
        }
        sPr[q*64 + c] = pr;
        sPv[q*64 + c] = pv;
    }

    // ---- per-(warp,pixel) square partials ----
    {
        float s0r=0.f, s1r=0.f, s0v=0.f, s1v=0.f;
#pragma unroll
        for (int o = 0; o < 8; o++) {
            s0r = fmaf(accr[0][o], accr[0][o], s0r);
            s1r = fmaf(accr[1][o], accr[1][o], s1r);
            s0v = fmaf(accv[0][o], accv[0][o], s0v);
            s1v = fmaf(accv[1][o], accv[1][o], s1v);
        }
        sSQR[wid*64 + p0] = s0r; sSQR[wid*64 + p1] = s1r;
        sSQV[wid*64 + p0] = s0v; sSQV[wid*64 + p1] = s1v;
    }
    __syncthreads();

    const float yy = -1.f + 2.f * (float)h / 63.f;
    if (tid < 64) {
        const int pix = tid;
        float ssr = 0.f, ssv = 0.f;
#pragma unroll
        for (int w = 0; w < 8; w++) { ssr += sSQR[w*64 + pix]; ssv += sSQV[w*64 + pix]; }
        const float sr = 1.f / fmaxf(sqrtf(ssr), 1e-6f);
        const float sv = 1.f / fmaxf(sqrtf(ssv), 1e-6f);
        const float e  = ssr * sr * sr;
        const float g  = expf(-2.f*yy*yy) * sGx[pix] * inv_gsum;
        const float swraw = e * g;
        sFr[pix] = sr * swraw;
        sSv[pix] = sv;
        sSw[pix] = swraw;
        // pools to global
        const float gyn = expf(-2.f*yy*yy) * inv_gsum;
        const int c = tid;
        g_poolr[(b*NH + h)*NC + c] = (sPr[c] + sPr[64+c] + sPr[128+c] + sPr[192+c]) * gyn;
        g_poolv[(b*NH + h)*NC + c] = (sPv[c] + sPv[64+c] + sPv[128+c] + sPv[192+c]) * gyn;
    }
    __syncthreads();

    if (tid == 0) {
        float s = 0.f;
        for (int i = 0; i < 64; i++) s += sSw[i];
        g_Spart[b*NH + h] = s;
    }

    // ---- scale accums and re-stage into sX (raw x now dead) ----
    {
        const float fr0 = sFr[p0], fr1 = sFr[p1];
        const float sv0 = sSv[p0], sv1 = sSv[p1];
        float4 t;
        t.x=accr[0][0]*fr0; t.y=accr[0][1]*fr0; t.z=accr[0][2]*fr0; t.w=accr[0][3]*fr0;
        *(float4*)&sXr[p0*68 + og] = t;
        t.x=accr[0][4]*fr0; t.y=accr[0][5]*fr0; t.z=accr[0][6]*fr0; t.w=accr[0][7]*fr0;
        *(float4*)&sXr[p0*68 + og + 4] = t;
        t.x=accr[1][0]*fr1; t.y=accr[1][1]*fr1; t.z=accr[1][2]*fr1; t.w=accr[1][3]*fr1;
        *(float4*)&sXr[p1*68 + og] = t;
        t.x=accr[1][4]*fr1; t.y=accr[1][5]*fr1; t.z=accr[1][6]*fr1; t.w=accr[1][7]*fr1;
        *(float4*)&sXr[p1*68 + og + 4] = t;
        t.x=accv[0][0]*sv0; t.y=accv[0][1]*sv0; t.z=accv[0][2]*sv0; t.w=accv[0][3]*sv0;
        *(float4*)&sXv[p0*68 + og] = t;
        t.x=accv[0][4]*sv0; t.y=accv[0][5]*sv0; t.z=accv[0][6]*sv0; t.w=accv[0][7]*sv0;
        *(float4*)&sXv[p0*68 + og + 4] = t;
        t.x=accv[1][0]*sv1; t.y=accv[1][1]*sv1; t.z=accv[1][2]*sv1; t.w=accv[1][3]*sv1;
        *(float4*)&sXv[p1*68 + og] = t;
        t.x=accv[1][4]*sv1; t.y=accv[1][5]*sv1; t.z=accv[1][6]*sv1; t.w=accv[1][7]*sv1;
        *(float4*)&sXv[p1*68 + og + 4] = t;
    }
    __syncthreads();

    // ---- coalesced global stores (pixel-major [b][pix][c]) ----
    {
        const size_t gbase = ((size_t)(b*NPIX + h*64)) * NC;
#pragma unroll
        for (int k = 0; k < 4; k++) {
            const int idx = k*256 + tid;        // float4 index 0..1023
            const int pix = idx >> 4;
            const int c4  = (idx & 15) * 4;
            *(float4*)&g_rubinw[gbase + pix*64 + c4] = *(float4*)&sXr[pix*68 + c4];
            *(float4*)&g_visn  [gbase + pix*64 + c4] = *(float4*)&sXv[pix*68 + c4];
        }
    }
}

// =========================== Kernel B =======================================
// Correlation costs. Block = (b, 8-row tile). 128 threads; each owns 4 adjacent
// columns (row = tid&7, cg = tid>>3). Sliding register window over dx.
// Dynamic smem: vis tile [4 cc4][14 rows][65 cols] float4  = 58240 B.
__global__ void __launch_bounds__(128, 3)
kB()
{
    const int tile = blockIdx.x;            // 0..7
    const int b    = blockIdx.y;
    const int h0   = tile * 8;
    const int tid  = threadIdx.x;
    const int row  = tid & 7;
    const int cg   = tid >> 3;              // 0..15, columns 4cg..4cg+3

    extern __shared__ float4 sv[];          // [(cc4*14 + r)*65 + col]

    float acc[KK];
#pragma unroll
    for (int k = 0; k < KK; k++) acc[k] = 0.f;

    for (int c0 = 0; c0 < 64; c0 += 16) {
        __syncthreads();
        for (int idx = tid; idx < 14*64*4; idx += 128) {
            int cc4 = idx & 3, col = (idx >> 2) & 63, r = idx >> 8;
            int gr = min(max(h0 + r - 3, 0), 63);
            sv[(cc4*14 + r)*65 + col] =
                *(const float4*)(g_visn + ((size_t)(b*NPIX + gr*64 + col))*NC + c0 + cc4*4);
        }
        __syncthreads();

        for (int cc4 = 0; cc4 < 4; cc4++) {
            float4 rb[4];
#pragma unroll
            for (int p = 0; p < 4; p++)
                rb[p] = *(const float4*)(g_rubinw +
                        ((size_t)(b*NPIX + (h0 + row)*64 + cg*4 + p))*NC + c0 + cc4*4);
#pragma unroll
            for (int dy = 0; dy < 7; dy++) {
                const float4* base = &sv[(cc4*14 + row + dy)*65];
                float4 w[10];
#pragma unroll
                for (int j = 0; j < 10; j++) {
                    int col = min(max(cg*4 + j - 3, 0), 63);
                    w[j] = base[col];
                }
#pragma unroll
                for (int dx = 0; dx < 7; dx++) {
#pragma unroll
                    for (int p = 0; p < 4; p++) {
                        float4 ww = w[p + dx];
                        float s = acc[dy*7 + dx];
                        s = fmaf(rb[p].x, ww.x, s);
                        s = fmaf(rb[p].y, ww.y, s);
                        s = fmaf(rb[p].z, ww.z, s);
                        s = fmaf(rb[p].w, ww.w, s);
                        acc[dy*7 + dx] = s;
                    }
                }
            }
        }
    }

    __shared__ float sred[4][KK];
    const int wid = tid >> 5, lane = tid & 31;
#pragma unroll
    for (int k = 0; k < KK; k++) {
        float v = acc[k];
#pragma unroll
        for (int off = 16; off > 0; off >>= 1) v += __shfl_down_sync(0xffffffffu, v, off);
        if (lane == 0) sred[wid][k] = v;
    }
    __syncthreads();
    if (tid < KK)
        g_costpart[(b*8 + tile)*KK + tid] =
            sred[0][tid] + sred[1][tid] + sred[2][tid] + sred[3][tid];
}

// =========================== Kernel C =======================================
__device__ __forceinline__ float gelu_exact(float x) {
    return 0.5f * x * (1.f + erff(x * 0.70710678118654752440f));
}

__global__ void __launch_bounds__(128)
kC(const float* __restrict__ p2s, const int* __restrict__ band_idx,
   const float* __restrict__ log_temp, const float* __restrict__ band_emb,
   const float* __restrict__ w1, const float* __restrict__ b1,
   const float* __restrict__ w2, const float* __restrict__ b2,
   const float* __restrict__ w3, const float* __restrict__ b3,
   float* __restrict__ out, int stride)
{
    const int b = blockIdx.x, tid = threadIdx.x;
    __shared__ float sfeat[212];
    __shared__ float scost[KK];
    __shared__ float sh1[128], sh2[128], sout3[3];
    __shared__ float sS, scdx, scdy, sconf;

    // deterministic partial reductions
    if (tid == 0) {
        float s = 0.f;
        for (int h = 0; h < NH; h++) s += g_Spart[b*NH + h];
        sS = s;
    }
    if (tid < KK) {
        float c = 0.f;
        for (int t = 0; t < 8; t++) c += g_costpart[(b*8 + t)*KK + tid];
        scost[tid] = c;
    }
    if (tid < 64) {
        float pr = 0.f, pv = 0.f;
        for (int h = 0; h < NH; h++) {
            pr += g_poolr[(b*NH + h)*NC + tid];
            pv += g_poolv[(b*NH + h)*NC + tid];
        }
        sfeat[tid] = pr; sfeat[64 + tid] = pv; sfeat[128 + tid] = pr - pv;
    }
    __syncthreads();

    if (tid == 0) {
        const float temp  = fmaxf(expf(log_temp[0]), 1e-3f);
        const float scale = 1.f / ((sS + 1e-8f) * 8.f * temp);  // sqrt(C)=8
        float l[KK], mx = -1e30f;
        for (int k = 0; k < KK; k++) { l[k] = scost[k] * scale; mx = fmaxf(mx, l[k]); }
        float sum = 0.f;
        for (int k = 0; k < KK; k++) { float p = expf(l[k] - mx); l[k] = p; sum += p; }
        const float inv = 1.f / sum;
        float cdx = 0.f, cdy = 0.f, cf = 0.f;
        for (int k = 0; k < KK; k++) {
            float p = l[k] * inv;
            cf  = fmaxf(cf, p);
            cdx += p * (float)((k % 7) - 3);
            cdy += p * (float)((k / 7) - 3);
        }
        scdx = cdx; scdy = cdy; sconf = cf;
        sfeat[192] = cdx; sfeat[193] = cdy;
    }
    if (tid < 16) sfeat[194 + tid] = band_emb[band_idx[b]*16 + tid];
    __syncthreads();

    float a = b1[tid];
    for (int f = 0; f < 210; f++) a = fmaf(sfeat[f], w1[f*128 + tid], a);
    sh1[tid] = gelu_exact(a);
    __syncthreads();

    a = b2[tid];
    for (int f = 0; f < 128; f++) a = fmaf(sh1[f], w2[f*128 + tid], a);
    sh2[tid] = gelu_exact(a);
    __syncthreads();

    if (tid < 3) {
        float a3 = b3[tid];
        for (int f = 0; f < 128; f++) a3 = fmaf(sh2[f], w3[f*3 + tid], a3);
        sout3[tid] = a3;
    }
    __syncthreads();

    if (tid == 0) {
        const float dx = scdx + sout3[0];
        const float dy = scdy + sout3[1];
        const float ls = fminf(fmaxf(sout3[2], -6.f), 3.f);
        const float s0 = p2s[b*4 + 0]*dx + p2s[b*4 + 1]*dy;
        const float s1 = p2s[b*4 + 2]*dx + p2s[b*4 + 3]*dy;
        float* o = out + (size_t)b * stride;
        if (stride > 0) o[0] = dx;
        if (stride > 1) o[1] = dy;
        if (stride > 2) o[2] = s0;
        if (stride > 3) o[3] = s1;
        if (stride > 4) o[4] = ls;
        if (stride > 5) o[5] = sconf;
        for (int j = 6; j < stride; j++) o[j] = 0.f;
    }
}

// =========================== launch =========================================
extern "C" void kernel_launch(void* const* d_in, const int* in_sizes, int n_in,
                              void* d_out, int out_size)
{
    const float* rubin = (const float*)d_in[0];
    const float* vis   = (const float*)d_in[1];
    const float* p2s   = (const float*)d_in[2];
    const int*   bidx  = (const int*)  d_in[3];
    const float* wr    = (const float*)d_in[4];
    const float* wv    = (const float*)d_in[5];
    const float* lt    = (const float*)d_in[6];
    const float* bemb  = (const float*)d_in[7];
    const float* w1    = (const float*)d_in[8];
    const float* b1    = (const float*)d_in[9];
    const float* w2    = (const float*)d_in[10];
    const float* b2    = (const float*)d_in[11];
    const float* w3    = (const float*)d_in[12];
    const float* b3    = (const float*)d_in[13];
    float* out = (float*)d_out;
    const int stride = out_size / NB;

    // gauss normalizer (separable, H=W=64)
    double Sy = 0.0;
    for (int i = 0; i < 64; i++) {
        double y = -1.0 + 2.0 * (double)i / 63.0;
        Sy += exp(-2.0 * y * y);
    }
    const float inv_gsum = (float)(1.0 / (Sy * Sy));

    const int ka_smem = KA_SMEM_FLOATS * 4;   // 76800 B
    cudaFuncSetAttribute(kA, cudaFuncAttributeMaxDynamicSharedMemorySize, ka_smem);
    const int kb_smem = 4 * 14 * 65 * 16;     // 58240 B
    cudaFuncSetAttribute(kB, cudaFuncAttributeMaxDynamicSharedMemorySize, kb_smem);

    kA<<<dim3(NH, NB), 256, ka_smem>>>(rubin, vis, wr, wv, inv_gsum);
    kB<<<dim3(8, NB), 128, kb_smem>>>();
    kC<<<NB, 128>>>(p2s, bidx, lt, bemb, w1, b1, w2, b2, w3, b3, out, stride);
}

// round 3
// speedup vs baseline: 1.5234x; 1.1071x over previous
#include <cuda_runtime.h>
#include <math.h>

#define NB   128   // batch
#define NC   64    // channels
#define NH   64
#define NW   64
#define NPIX (NH*NW)
#define KK   49

typedef unsigned long long u64;

// ---- packed fp32x2 helpers (sm_100+ PTX; full IEEE fp32 per lane) ----------
__device__ __forceinline__ u64 splat2(float a) {
    u64 r; asm("mov.b64 %0, {%1,%1};" : "=l"(r) : "f"(a)); return r;
}
__device__ __forceinline__ void fma2(u64& d, u64 a, u64 b) {
    asm("fma.rn.f32x2 %0, %1, %2, %0;" : "+l"(d) : "l"(a), "l"(b));
}
__device__ __forceinline__ float2 upk(u64 v) {
    float2 f; asm("mov.b64 {%0,%1}, %2;" : "=f"(f.x), "=f"(f.y) : "l"(v)); return f;
}
#define GETC(v,cc) ((cc)==0?(v).x:(cc)==1?(v).y:(cc)==2?(v).z:(v).w)

// ---------------- scratch (device globals; no allocations allowed) ----------
__device__ __align__(16) float g_rubinw[NB*NPIX*NC];   // rubin_n * swraw, [b][pix][c]
__device__ __align__(16) float g_visn  [NB*NPIX*NC];   // vis_n,           [b][pix][c]
__device__ float g_costpart[NB*8*KK];
__device__ float g_poolr[NB*NH*NC];
__device__ float g_poolv[NB*NH*NC];
__device__ float g_Spart[NB*NH];

// =========================== Kernel A =======================================
// One block per (b, row h). 256 threads, 8 warps.
// f32x2 register tile: thread owns 2 pixels (lane, lane+32) x 4 output-PAIRS
// (warp owns outputs 8*wid..8*wid+7) x 2 tensors -> 16 u64 accumulators.
// Weights staged [c][o] so LDS.128 yields two aligned (w[o],w[o+1]) pairs.
#define OFF_WR  0
#define OFF_WV  4352
#define OFF_XR  8704
#define OFF_XV  13056
#define OFF_SQR 17408
#define OFF_SQV 17920
#define OFF_PR  18432
#define OFF_PV  18688
#define OFF_GX  18944
#define OFF_FR  19008
#define OFF_SV  19072
#define OFF_SW  19136
#define KA_SMEM_FLOATS 19200

__global__ void __launch_bounds__(256, 2)
kA(const float* __restrict__ rubin, const float* __restrict__ vis,
   const float* __restrict__ wr, const float* __restrict__ wv, float inv_gsum)
{
    extern __shared__ float sm[];
    float* sWr = sm + OFF_WR;    // [c][o], stride 68
    float* sWv = sm + OFF_WV;
    float* sXr = sm + OFF_XR;    // [pix][c], stride 68
    float* sXv = sm + OFF_XV;
    float* sSQR = sm + OFF_SQR;  // [8][64]
    float* sSQV = sm + OFF_SQV;
    float* sPr = sm + OFF_PR;    // [4][64]
    float* sPv = sm + OFF_PV;
    float* sGx = sm + OFF_GX;    // [64]
    float* sFr = sm + OFF_FR;    // [64]
    float* sSv = sm + OFF_SV;    // [64]
    float* sSw = sm + OFF_SW;    // [64]

    const int h = blockIdx.x, b = blockIdx.y;
    const int tid = threadIdx.x;
    const int wid = tid >> 5, lane = tid & 31;

    // ---- weights -> smem transposed [c][o] (coalesced global read) ----
    for (int idx = tid; idx < 4096; idx += 256) {
        int o = idx >> 6, c = idx & 63;
        sWr[c*68 + o] = wr[idx];
        sWv[c*68 + o] = wv[idx];
    }
    if (tid < 64) {
        float xxg = -1.f + 2.f * (float)tid / 63.f;
        sGx[tid] = expf(-2.f * xxg * xxg);
    }

    // ---- stage x transposed: sX[pix][c] ----
    {
        const int w0 = tid & 63, cq = tid >> 6;
        const size_t rowbase = (size_t)b*NC*NPIX + (size_t)h*64 + w0;
#pragma unroll
        for (int it = 0; it < 4; it++) {
            int c0 = cq*4 + it*16;
            float4 vr, vv;
            vr.x = rubin[rowbase + (size_t)(c0+0)*NPIX];
            vr.y = rubin[rowbase + (size_t)(c0+1)*NPIX];
            vr.z = rubin[rowbase + (size_t)(c0+2)*NPIX];
            vr.w = rubin[rowbase + (size_t)(c0+3)*NPIX];
            vv.x = vis  [rowbase + (size_t)(c0+0)*NPIX];
            vv.y = vis  [rowbase + (size_t)(c0+1)*NPIX];
            vv.z = vis  [rowbase + (size_t)(c0+2)*NPIX];
            vv.w = vis  [rowbase + (size_t)(c0+3)*NPIX];
            *(float4*)&sXr[w0*68 + c0] = vr;
            *(float4*)&sXv[w0*68 + c0] = vv;
        }
    }
    __syncthreads();

    // ---- f32x2 register-tiled GEMM ----
    const int og = wid * 8;
    const int p0 = lane, p1 = lane + 32;
    u64 acr[2][4], acv[2][4];          // [pixel][output-pair]
#pragma unroll
    for (int j = 0; j < 4; j++) { acr[0][j]=0ull; acr[1][j]=0ull; acv[0][j]=0ull; acv[1][j]=0ull; }

#pragma unroll 4
    for (int c0 = 0; c0 < 64; c0 += 4) {
        const float4 x0r = *(const float4*)&sXr[p0*68 + c0];
        const float4 x1r = *(const float4*)&sXr[p1*68 + c0];
        const float4 x0v = *(const float4*)&sXv[p0*68 + c0];
        const float4 x1v = *(const float4*)&sXv[p1*68 + c0];
#pragma unroll
        for (int cc = 0; cc < 4; cc++) {
            const int c = c0 + cc;
            const ulonglong2 wra = *(const ulonglong2*)&sWr[c*68 + og];      // o pairs (0,1),(2,3)
            const ulonglong2 wrb = *(const ulonglong2*)&sWr[c*68 + og + 4];  // (4,5),(6,7)
            const ulonglong2 wva = *(const ulonglong2*)&sWv[c*68 + og];
            const ulonglong2 wvb = *(const ulonglong2*)&sWv[c*68 + og + 4];
            const u64 s0r = splat2(GETC(x0r, cc));
            const u64 s1r = splat2(GETC(x1r, cc));
            const u64 s0v = splat2(GETC(x0v, cc));
            const u64 s1v = splat2(GETC(x1v, cc));
            fma2(acr[0][0], wra.x, s0r); fma2(acr[0][1], wra.y, s0r);
            fma2(acr[0][2], wrb.x, s0r); fma2(acr[0][3], wrb.y, s0r);
            fma2(acr[1][0], wra.x, s1r); fma2(acr[1][1], wra.y, s1r);
            fma2(acr[1][2], wrb.x, s1r); fma2(acr[1][3], wrb.y, s1r);
            fma2(acv[0][0], wva.x, s0v); fma2(acv[0][1], wva.y, s0v);
            fma2(acv[0][2], wvb.x, s0v); fma2(acv[0][3], wvb.y, s0v);
            fma2(acv[1][0], wva.x, s1v); fma2(acv[1][1], wva.y, s1v);
            fma2(acv[1][2], wvb.x, s1v); fma2(acv[1][3], wvb.y, s1v);
        }
    }

    // ---- unpack accumulators ----
    float accr[2][8], accv[2][8];
#pragma unroll
    for (int p = 0; p < 2; p++)
#pragma unroll
        for (int j = 0; j < 4; j++) {
            float2 t = upk(acr[p][j]); accr[p][2*j] = t.x; accr[p][2*j+1] = t.y;
            float2 u = upk(acv[p][j]); accv[p][2*j] = u.x; accv[p][2*j+1] = u.y;
        }

    // ---- pool partials over raw x (still resident in sX) ----
    {
        const int c = tid & 63, q = tid >> 6;
        float pr = 0.f, pv = 0.f;
#pragma unroll
        for (int w = 0; w < 16; w++) {
            const int px = q*16 + w;
            const float gxw = sGx[px];
            pr = fmaf(sXr[px*68 + c], gxw, pr);
            pv = fmaf(sXv[px*68 + c], gxw, pv);
        }
        sPr[q*64 + c] = pr;
        sPv[q*64 + c] = pv;
    }

    // ---- per-(warp,pixel) square partials ----
    {
        float s0r=0.f, s1r=0.f, s0v=0.f, s1v=0.f;
#pragma unroll
        for (int o = 0; o < 8; o++) {
            s0r = fmaf(accr[0][o], accr[0][o], s0r);
            s1r = fmaf(accr[1][o], accr[1][o], s1r);
            s0v = fmaf(accv[0][o], accv[0][o], s0v);
            s1v = fmaf(accv[1][o], accv[1][o], s1v);
        }
        sSQR[wid*64 + p0] = s0r; sSQR[wid*64 + p1] = s1r;
        sSQV[wid*64 + p0] = s0v; sSQV[wid*64 + p1] = s1v;
    }
    __syncthreads();

    const float yy = -1.f + 2.f * (float)h / 63.f;
    if (tid < 64) {
        const int pix = tid;
        float ssr = 0.f, ssv = 0.f;
#pragma unroll
        for (int w = 0; w < 8; w++) { ssr += sSQR[w*64 + pix]; ssv += sSQV[w*64 + pix]; }
        const float sr = 1.f / fmaxf(sqrtf(ssr), 1e-6f);
        const float sv = 1.f / fmaxf(sqrtf(ssv), 1e-6f);
        const float e  = ssr * sr * sr;
        const float g  = expf(-2.f*yy*yy) * sGx[pix] * inv_gsum;
        const float swraw = e * g;
        sFr[pix] = sr * swraw;
        sSv[pix] = sv;
        sSw[pix] = swraw;
        const float gyn = expf(-2.f*yy*yy) * inv_gsum;
        const int c = tid;
        g_poolr[(b*NH + h)*NC + c] = (sPr[c] + sPr[64+c] + sPr[128+c] + sPr[192+c]) * gyn;
        g_poolv[(b*NH + h)*NC + c] = (sPv[c] + sPv[64+c] + sPv[128+c] + sPv[192+c]) * gyn;
    }
    __syncthreads();

    if (tid == 0) {
        float s = 0.f;
        for (int i = 0; i < 64; i++) s += sSw[i];
        g_Spart[b*NH + h] = s;
    }

    // ---- scale accums and re-stage into sX (raw x now dead) ----
    {
        const float fr0 = sFr[p0], fr1 = sFr[p1];
        const float sv0 = sSv[p0], sv1 = sSv[p1];
        float4 t;
        t.x=accr[0][0]*fr0; t.y=accr[0][1]*fr0; t.z=accr[0][2]*fr0; t.w=accr[0][3]*fr0;
        *(float4*)&sXr[p0*68 + og] = t;
        t.x=accr[0][4]*fr0; t.y=accr[0][5]*fr0; t.z=accr[0][6]*fr0; t.w=accr[0][7]*fr0;
        *(float4*)&sXr[p0*68 + og + 4] = t;
        t.x=accr[1][0]*fr1; t.y=accr[1][1]*fr1; t.z=accr[1][2]*fr1; t.w=accr[1][3]*fr1;
        *(float4*)&sXr[p1*68 + og] = t;
        t.x=accr[1][4]*fr1; t.y=accr[1][5]*fr1; t.z=accr[1][6]*fr1; t.w=accr[1][7]*fr1;
        *(float4*)&sXr[p1*68 + og + 4] = t;
        t.x=accv[0][0]*sv0; t.y=accv[0][1]*sv0; t.z=accv[0][2]*sv0; t.w=accv[0][3]*sv0;
        *(float4*)&sXv[p0*68 + og] = t;
        t.x=accv[0][4]*sv0; t.y=accv[0][5]*sv0; t.z=accv[0][6]*sv0; t.w=accv[0][7]*sv0;
        *(float4*)&sXv[p0*68 + og + 4] = t;
        t.x=accv[1][0]*sv1; t.y=accv[1][1]*sv1; t.z=accv[1][2]*sv1; t.w=accv[1][3]*sv1;
        *(float4*)&sXv[p1*68 + og] = t;
        t.x=accv[1][4]*sv1; t.y=accv[1][5]*sv1; t.z=accv[1][6]*sv1; t.w=accv[1][7]*sv1;
        *(float4*)&sXv[p1*68 + og + 4] = t;
    }
    __syncthreads();

    // ---- coalesced global stores (pixel-major [b][pix][c]) ----
    {
        const size_t gbase = ((size_t)(b*NPIX + h*64)) * NC;
#pragma unroll
        for (int k = 0; k < 4; k++) {
            const int idx = k*256 + tid;
            const int pix = idx >> 4;
            const int c4  = (idx & 15) * 4;
            *(float4*)&g_rubinw[gbase + pix*64 + c4] = *(float4*)&sXr[pix*68 + c4];
            *(float4*)&g_visn  [gbase + pix*64 + c4] = *(float4*)&sXv[pix*68 + c4];
        }
    }
}

// =========================== Kernel B =======================================
// Correlation costs with f32x2 over channel pairs. Block = (b, 8-row tile).
// 128 threads; each owns 4 adjacent columns. 49 u64 accumulators.
__global__ void __launch_bounds__(128, 2)
kB()
{
    const int tile = blockIdx.x;            // 0..7
    const int b    = blockIdx.y;
    const int h0   = tile * 8;
    const int tid  = threadIdx.x;
    const int row  = tid & 7;
    const int cg   = tid >> 3;              // 0..15, columns 4cg..4cg+3

    extern __shared__ ulonglong2 sv[];      // [(cc4*14 + r)*65 + col]

    u64 acc2[KK];
#pragma unroll
    for (int k = 0; k < KK; k++) acc2[k] = 0ull;

    for (int c0 = 0; c0 < 64; c0 += 16) {
        __syncthreads();
        for (int idx = tid; idx < 14*64*4; idx += 128) {
            int cc4 = idx & 3, col = (idx >> 2) & 63, r = idx >> 8;
            int gr = min(max(h0 + r - 3, 0), 63);
            sv[(cc4*14 + r)*65 + col] =
                *(const ulonglong2*)(g_visn + ((size_t)(b*NPIX + gr*64 + col))*NC + c0 + cc4*4);
        }
        __syncthreads();

        for (int cc4 = 0; cc4 < 4; cc4++) {
            ulonglong2 rb[4];
#pragma unroll
            for (int p = 0; p < 4; p++)
                rb[p] = *(const ulonglong2*)(g_rubinw +
                        ((size_t)(b*NPIX + (h0 + row)*64 + cg*4 + p))*NC + c0 + cc4*4);
#pragma unroll
            for (int dy = 0; dy < 7; dy++) {
                const ulonglong2* base = &sv[(cc4*14 + row + dy)*65];
                ulonglong2 w[10];
#pragma unroll
                for (int j = 0; j < 10; j++) {
                    int col = min(max(cg*4 + j - 3, 0), 63);
                    w[j] = base[col];
                }
#pragma unroll
                for (int dx = 0; dx < 7; dx++) {
#pragma unroll
                    for (int p = 0; p < 4; p++) {
                        fma2(acc2[dy*7 + dx], rb[p].x, w[p + dx].x);
                        fma2(acc2[dy*7 + dx], rb[p].y, w[p + dx].y);
                    }
                }
            }
        }
    }

    __shared__ float sred[4][KK];
    const int wid = tid >> 5, lane = tid & 31;
#pragma unroll
    for (int k = 0; k < KK; k++) {
        float2 t = upk(acc2[k]);
        float v = t.x + t.y;
#pragma unroll
        for (int off = 16; off > 0; off >>= 1) v += __shfl_down_sync(0xffffffffu, v, off);
        if (lane == 0) sred[wid][k] = v;
    }
    __syncthreads();
    if (tid < KK)
        g_costpart[(b*8 + tile)*KK + tid] =
            sred[0][tid] + sred[1][tid] + sred[2][tid] + sred[3][tid];
}

// =========================== Kernel C =======================================
__device__ __forceinline__ float gelu_exact(float x) {
    return 0.5f * x * (1.f + erff(x * 0.70710678118654752440f));
}

__global__ void __launch_bounds__(128)
kC(const float* __restrict__ p2s, const int* __restrict__ band_idx,
   const float* __restrict__ log_temp, const float* __restrict__ band_emb,
   const float* __restrict__ w1, const float* __restrict__ b1,
   const float* __restrict__ w2, const float* __restrict__ b2,
   const float* __restrict__ w3, const float* __restrict__ b3,
   float* __restrict__ out, int stride)
{
    const int b = blockIdx.x, tid = threadIdx.x;
    __shared__ float sfeat[212];
    __shared__ float scost[KK];
    __shared__ float sh1[128], sh2[128], sout3[3];
    __shared__ float sS, scdx, scdy, sconf;

    if (tid == 0) {
        float s = 0.f;
        for (int h = 0; h < NH; h++) s += g_Spart[b*NH + h];
        sS = s;
    }
    if (tid < KK) {
        float c = 0.f;
        for (int t = 0; t < 8; t++) c += g_costpart[(b*8 + t)*KK + tid];
        scost[tid] = c;
    }
    if (tid < 64) {
        float pr = 0.f, pv = 0.f;
        for (int h = 0; h < NH; h++) {
            pr += g_poolr[(b*NH + h)*NC + tid];
            pv += g_poolv[(b*NH + h)*NC + tid];
        }
        sfeat[tid] = pr; sfeat[64 + tid] = pv; sfeat[128 + tid] = pr - pv;
    }
    __syncthreads();

    if (tid == 0) {
        const float temp  = fmaxf(expf(log_temp[0]), 1e-3f);
        const float scale = 1.f / ((sS + 1e-8f) * 8.f * temp);  // sqrt(C)=8
        float l[KK], mx = -1e30f;
        for (int k = 0; k < KK; k++) { l[k] = scost[k] * scale; mx = fmaxf(mx, l[k]); }
        float sum = 0.f;
        for (int k = 0; k < KK; k++) { float p = expf(l[k] - mx); l[k] = p; sum += p; }
        const float inv = 1.f / sum;
        float cdx = 0.f, cdy = 0.f, cf = 0.f;
        for (int k = 0; k < KK; k++) {
            float p = l[k] * inv;
            cf  = fmaxf(cf, p);
            cdx += p * (float)((k % 7) - 3);
            cdy += p * (float)((k / 7) - 3);
        }
        scdx = cdx; scdy = cdy; sconf = cf;
        sfeat[192] = cdx; sfeat[193] = cdy;
    }
    if (tid < 16) sfeat[194 + tid] = band_emb[band_idx[b]*16 + tid];
    __syncthreads();

    float a = b1[tid];
    for (int f = 0; f < 210; f++) a = fmaf(sfeat[f], w1[f*128 + tid], a);
    sh1[tid] = gelu_exact(a);
    __syncthreads();

    a = b2[tid];
    for (int f = 0; f < 128; f++) a = fmaf(sh1[f], w2[f*128 + tid], a);
    sh2[tid] = gelu_exact(a);
    __syncthreads();

    if (tid < 3) {
        float a3 = b3[tid];
        for (int f = 0; f < 128; f++) a3 = fmaf(sh2[f], w3[f*3 + tid], a3);
        sout3[tid] = a3;
    }
    __syncthreads();

    if (tid == 0) {
        const float dx = scdx + sout3[0];
        const float dy = scdy + sout3[1];
        const float ls = fminf(fmaxf(sout3[2], -6.f), 3.f);
        const float s0 = p2s[b*4 + 0]*dx + p2s[b*4 + 1]*dy;
        const float s1 = p2s[b*4 + 2]*dx + p2s[b*4 + 3]*dy;
        float* o = out + (size_t)b * stride;
        if (stride > 0) o[0] = dx;
        if (stride > 1) o[1] = dy;
        if (stride > 2) o[2] = s0;
        if (stride > 3) o[3] = s1;
        if (stride > 4) o[4] = ls;
        if (stride > 5) o[5] = sconf;
        for (int j = 6; j < stride; j++) o[j] = 0.f;
    }
}

// =========================== launch =========================================
extern "C" void kernel_launch(void* const* d_in, const int* in_sizes, int n_in,
                              void* d_out, int out_size)
{
    const float* rubin = (const float*)d_in[0];
    const float* vis   = (const float*)d_in[1];
    const float* p2s   = (const float*)d_in[2];
    const int*   bidx  = (const int*)  d_in[3];
    const float* wr    = (const float*)d_in[4];
    const float* wv    = (const float*)d_in[5];
    const float* lt    = (const float*)d_in[6];
    const float* bemb  = (const float*)d_in[7];
    const float* w1    = (const float*)d_in[8];
    const float* b1    = (const float*)d_in[9];
    const float* w2    = (const float*)d_in[10];
    const float* b2    = (const float*)d_in[11];
    const float* w3    = (const float*)d_in[12];
    const float* b3    = (const float*)d_in[13];
    float* out = (float*)d_out;
    const int stride = out_size / NB;

    // gauss normalizer (separable, H=W=64)
    double Sy = 0.0;
    for (int i = 0; i < 64; i++) {
        double y = -1.0 + 2.0 * (double)i / 63.0;
        Sy += exp(-2.0 * y * y);
    }
    const float inv_gsum = (float)(1.0 / (Sy * Sy));

    const int ka_smem = KA_SMEM_FLOATS * 4;   // 76800 B
    cudaFuncSetAttribute(kA, cudaFuncAttributeMaxDynamicSharedMemorySize, ka_smem);
    const int kb_smem = 4 * 14 * 65 * 16;     // 58240 B
    cudaFuncSetAttribute(kB, cudaFuncAttributeMaxDynamicSharedMemorySize, kb_smem);

    kA<<<dim3(NH, NB), 256, ka_smem>>>(rubin, vis, wr, wv, inv_gsum);
    kB<<<dim3(8, NB), 128, kb_smem>>>();
    kC<<<NB, 128>>>(p2s, bidx, lt, bemb, w1, b1, w2, b2, w3, b3, out, stride);
}

// round 4
// speedup vs baseline: 1.6260x; 1.0673x over previous
#include <cuda_runtime.h>
#include <math.h>

#define NB   128   // batch
#define NC   64    // channels
#define NH   64
#define NW   64
#define NPIX (NH*NW)
#define KK   49

typedef unsigned long long u64;

// ---- packed fp32x2 helpers (sm_100+ PTX; full IEEE fp32 per lane) ----------
__device__ __forceinline__ u64 splat2(float a) {
    u64 r; asm("mov.b64 %0, {%1,%1};" : "=l"(r) : "f"(a)); return r;
}
__device__ __forceinline__ void fma2(u64& d, u64 a, u64 b) {
    asm("fma.rn.f32x2 %0, %1, %2, %0;" : "+l"(d) : "l"(a), "l"(b));
}
__device__ __forceinline__ float2 upk(u64 v) {
    float2 f; asm("mov.b64 {%0,%1}, %2;" : "=f"(f.x), "=f"(f.y) : "l"(v)); return f;
}
#define GETC(v,cc) ((cc)==0?(v).x:(cc)==1?(v).y:(cc)==2?(v).z:(v).w)

// ---------------- scratch (device globals; no allocations allowed) ----------
__device__ __align__(16) float g_rubinw[NB*NPIX*NC];   // rubin_n * swraw, [b][pix][c]
__device__ __align__(16) float g_visn  [NB*NPIX*NC];   // vis_n,           [b][pix][c]
__device__ float g_costpart[NB*8*KK];
__device__ float g_poolr[NB*NH*NC];
__device__ float g_poolv[NB*NH*NC];
__device__ float g_Spart[NB*NH];

// =========================== Kernel A =======================================
// One block per (b, row h). 256 threads, 8 warps, TENSOR-SPECIALIZED:
// warps 0-3 -> rubin, warps 4-7 -> vis. Each warp owns 16 outputs
// (og = (wid&3)*16); each thread owns 2 pixels (lane, lane+32) x 8 output-
// pairs of its tensor -> 16 u64 f32x2 accumulators.
// Per 4-channel step per warp: 2 distinct x LDS.128 + 16 broadcast weight
// LDS.128 -> FMA pipe binds, not the smem crossbar.
#define OFF_WR  0
#define OFF_WV  4352
#define OFF_XR  8704
#define OFF_XV  13056
#define OFF_SQR 17408
#define OFF_SQV 17664
#define OFF_PR  17920
#define OFF_PV  18176
#define OFF_GX  18432
#define OFF_FR  18496
#define OFF_SV  18560
#define OFF_SW  18624
#define KA_SMEM_FLOATS 18688

__global__ void __launch_bounds__(256, 2)
kA(const float* __restrict__ rubin, const float* __restrict__ vis,
   const float* __restrict__ wr, const float* __restrict__ wv, float inv_gsum)
{
    extern __shared__ float sm[];
    float* sWr = sm + OFF_WR;    // [c][o], stride 68
    float* sWv = sm + OFF_WV;
    float* sXr = sm + OFF_XR;    // [pix][c], stride 68
    float* sXv = sm + OFF_XV;
    float* sSQR = sm + OFF_SQR;  // [4][64]
    float* sSQV = sm + OFF_SQV;  // [4][64]
    float* sPr = sm + OFF_PR;    // [4][64]
    float* sPv = sm + OFF_PV;
    float* sGx = sm + OFF_GX;    // [64]
    float* sFr = sm + OFF_FR;    // [64]
    float* sSv = sm + OFF_SV;    // [64]
    float* sSw = sm + OFF_SW;    // [64]

    const int h = blockIdx.x, b = blockIdx.y;
    const int tid = threadIdx.x;
    const int wid = tid >> 5, lane = tid & 31;
    const bool isR = (wid < 4);

    // ---- weights -> smem transposed [c][o] (coalesced global read) ----
    for (int idx = tid; idx < 4096; idx += 256) {
        int o = idx >> 6, c = idx & 63;
        sWr[c*68 + o] = wr[idx];
        sWv[c*68 + o] = wv[idx];
    }
    if (tid < 64) {
        float xxg = -1.f + 2.f * (float)tid / 63.f;
        sGx[tid] = expf(-2.f * xxg * xxg);
    }

    // ---- stage x transposed: sX[pix][c] ----
    {
        const int w0 = tid & 63, cq = tid >> 6;
        const size_t rowbase = (size_t)b*NC*NPIX + (size_t)h*64 + w0;
#pragma unroll
        for (int it = 0; it < 4; it++) {
            int c0 = cq*4 + it*16;
            float4 vr, vv;
            vr.x = rubin[rowbase + (size_t)(c0+0)*NPIX];
            vr.y = rubin[rowbase + (size_t)(c0+1)*NPIX];
            vr.z = rubin[rowbase + (size_t)(c0+2)*NPIX];
            vr.w = rubin[rowbase + (size_t)(c0+3)*NPIX];
            vv.x = vis  [rowbase + (size_t)(c0+0)*NPIX];
            vv.y = vis  [rowbase + (size_t)(c0+1)*NPIX];
            vv.z = vis  [rowbase + (size_t)(c0+2)*NPIX];
            vv.w = vis  [rowbase + (size_t)(c0+3)*NPIX];
            *(float4*)&sXr[w0*68 + c0] = vr;
            *(float4*)&sXv[w0*68 + c0] = vv;
        }
    }
    __syncthreads();

    // ---- f32x2 register-tiled GEMM (one tensor per warp) ----
    const int og = (wid & 3) * 16;
    const int p0 = lane, p1 = lane + 32;
    const float* sX = isR ? sXr : sXv;
    const float* sW = isR ? sWr : sWv;

    u64 acc[2][8];     // [pixel][output-pair]
#pragma unroll
    for (int j = 0; j < 8; j++) { acc[0][j] = 0ull; acc[1][j] = 0ull; }

#pragma unroll 4
    for (int c0 = 0; c0 < 64; c0 += 4) {
        const float4 x0 = *(const float4*)&sX[p0*68 + c0];
        const float4 x1 = *(const float4*)&sX[p1*68 + c0];
#pragma unroll
        for (int cc = 0; cc < 4; cc++) {
            const int c = c0 + cc;
            const ulonglong2 wa = *(const ulonglong2*)&sW[c*68 + og];
            const ulonglong2 wb = *(const ulonglong2*)&sW[c*68 + og + 4];
            const ulonglong2 wc = *(const ulonglong2*)&sW[c*68 + og + 8];
            const ulonglong2 wd = *(const ulonglong2*)&sW[c*68 + og + 12];
            const u64 s0 = splat2(GETC(x0, cc));
            const u64 s1 = splat2(GETC(x1, cc));
            fma2(acc[0][0], wa.x, s0); fma2(acc[0][1], wa.y, s0);
            fma2(acc[0][2], wb.x, s0); fma2(acc[0][3], wb.y, s0);
            fma2(acc[0][4], wc.x, s0); fma2(acc[0][5], wc.y, s0);
            fma2(acc[0][6], wd.x, s0); fma2(acc[0][7], wd.y, s0);
            fma2(acc[1][0], wa.x, s1); fma2(acc[1][1], wa.y, s1);
            fma2(acc[1][2], wb.x, s1); fma2(acc[1][3], wb.y, s1);
            fma2(acc[1][4], wc.x, s1); fma2(acc[1][5], wc.y, s1);
            fma2(acc[1][6], wd.x, s1); fma2(acc[1][7], wd.y, s1);
        }
    }

    // ---- pool partials over raw x (still resident in sXr/sXv) ----
    {
        const int c = tid & 63, q = tid >> 6;
        float pr = 0.f, pv = 0.f;
#pragma unroll
        for (int w = 0; w < 16; w++) {
            const int px = q*16 + w;
            const float gxw = sGx[px];
            pr = fmaf(sXr[px*68 + c], gxw, pr);
            pv = fmaf(sXv[px*68 + c], gxw, pv);
        }
        sPr[q*64 + c] = pr;
        sPv[q*64 + c] = pv;
    }

    // ---- per-(warp,pixel) square partials over this warp's 16 outputs ----
    {
        float sq0 = 0.f, sq1 = 0.f;
#pragma unroll
        for (int j = 0; j < 8; j++) {
            float2 t0 = upk(acc[0][j]); sq0 = fmaf(t0.x, t0.x, fmaf(t0.y, t0.y, sq0));
            float2 t1 = upk(acc[1][j]); sq1 = fmaf(t1.x, t1.x, fmaf(t1.y, t1.y, sq1));
        }
        float* sSQ = isR ? sSQR : sSQV;
        sSQ[(wid & 3)*64 + p0] = sq0;
        sSQ[(wid & 3)*64 + p1] = sq1;
    }
    __syncthreads();

    const float yy = -1.f + 2.f * (float)h / 63.f;
    if (tid < 64) {
        const int pix = tid;
        float ssr = 0.f, ssv = 0.f;
#pragma unroll
        for (int w = 0; w < 4; w++) { ssr += sSQR[w*64 + pix]; ssv += sSQV[w*64 + pix]; }
        const float sr = 1.f / fmaxf(sqrtf(ssr), 1e-6f);
        const float sv = 1.f / fmaxf(sqrtf(ssv), 1e-6f);
        const float e  = ssr * sr * sr;
        const float g  = expf(-2.f*yy*yy) * sGx[pix] * inv_gsum;
        const float swraw = e * g;
        sFr[pix] = sr * swraw;
        sSv[pix] = sv;
        sSw[pix] = swraw;
        const float gyn = expf(-2.f*yy*yy) * inv_gsum;
        const int c = tid;
        g_poolr[(b*NH + h)*NC + c] = (sPr[c] + sPr[64+c] + sPr[128+c] + sPr[192+c]) * gyn;
        g_poolv[(b*NH + h)*NC + c] = (sPv[c] + sPv[64+c] + sPv[128+c] + sPv[192+c]) * gyn;
    }
    __syncthreads();

    if (tid == 0) {
        float s = 0.f;
        for (int i = 0; i < 64; i++) s += sSw[i];
        g_Spart[b*NH + h] = s;
    }

    // ---- scale accums and re-stage into own tensor's sX (raw x now dead) ----
    {
        float* sXo = isR ? sXr : sXv;
        const float f0 = isR ? sFr[p0] : sSv[p0];
        const float f1 = isR ? sFr[p1] : sSv[p1];
#pragma unroll
        for (int q = 0; q < 4; q++) {
            float2 ta = upk(acc[0][2*q]), tb = upk(acc[0][2*q+1]);
            float4 t; t.x = ta.x*f0; t.y = ta.y*f0; t.z = tb.x*f0; t.w = tb.y*f0;
            *(float4*)&sXo[p0*68 + og + 4*q] = t;
            float2 ua = upk(acc[1][2*q]), ub = upk(acc[1][2*q+1]);
            float4 u; u.x = ua.x*f1; u.y = ua.y*f1; u.z = ub.x*f1; u.w = ub.y*f1;
            *(float4*)&sXo[p1*68 + og + 4*q] = u;
        }
    }
    __syncthreads();

    // ---- coalesced global stores (pixel-major [b][pix][c]) ----
    {
        const size_t gbase = ((size_t)(b*NPIX + h*64)) * NC;
#pragma unroll
        for (int k = 0; k < 4; k++) {
            const int idx = k*256 + tid;
            const int pix = idx >> 4;
            const int c4  = (idx & 15) * 4;
            *(float4*)&g_rubinw[gbase + pix*64 + c4] = *(float4*)&sXr[pix*68 + c4];
            *(float4*)&g_visn  [gbase + pix*64 + c4] = *(float4*)&sXv[pix*68 + c4];
        }
    }
}

// =========================== Kernel B =======================================
// Correlation costs with f32x2 over channel pairs. Block = (b, 8-row tile).
// 128 threads; each owns 4 adjacent columns. 49 u64 accumulators.
__global__ void __launch_bounds__(128, 2)
kB()
{
    const int tile = blockIdx.x;            // 0..7
    const int b    = blockIdx.y;
    const int h0   = tile * 8;
    const int tid  = threadIdx.x;
    const int row  = tid & 7;
    const int cg   = tid >> 3;              // 0..15, columns 4cg..4cg+3

    extern __shared__ ulonglong2 sv[];      // [(cc4*14 + r)*65 + col]

    u64 acc2[KK];
#pragma unroll
    for (int k = 0; k < KK; k++) acc2[k] = 0ull;

    for (int c0 = 0; c0 < 64; c0 += 16) {
        __syncthreads();
        for (int idx = tid; idx < 14*64*4; idx += 128) {
            int cc4 = idx & 3, col = (idx >> 2) & 63, r = idx >> 8;
            int gr = min(max(h0 + r - 3, 0), 63);
            sv[(cc4*14 + r)*65 + col] =
                *(const ulonglong2*)(g_visn + ((size_t)(b*NPIX + gr*64 + col))*NC + c0 + cc4*4);
        }
        __syncthreads();

        for (int cc4 = 0; cc4 < 4; cc4++) {
            ulonglong2 rb[4];
#pragma unroll
            for (int p = 0; p < 4; p++)
                rb[p] = *(const ulonglong2*)(g_rubinw +
                        ((size_t)(b*NPIX + (h0 + row)*64 + cg*4 + p))*NC + c0 + cc4*4);
#pragma unroll
            for (int dy = 0; dy < 7; dy++) {
                const ulonglong2* base = &sv[(cc4*14 + row + dy)*65];
                ulonglong2 w[10];
#pragma unroll
                for (int j = 0; j < 10; j++) {
                    int col = min(max(cg*4 + j - 3, 0), 63);
                    w[j] = base[col];
                }
#pragma unroll
                for (int dx = 0; dx < 7; dx++) {
#pragma unroll
                    for (int p = 0; p < 4; p++) {
                        fma2(acc2[dy*7 + dx], rb[p].x, w[p + dx].x);
                        fma2(acc2[dy*7 + dx], rb[p].y, w[p + dx].y);
                    }
                }
            }
        }
    }

    __shared__ float sred[4][KK];
    const int wid = tid >> 5, lane = tid & 31;
#pragma unroll
    for (int k = 0; k < KK; k++) {
        float2 t = upk(acc2[k]);
        float v = t.x + t.y;
#pragma unroll
        for (int off = 16; off > 0; off >>= 1) v += __shfl_down_sync(0xffffffffu, v, off);
        if (lane == 0) sred[wid][k] = v;
    }
    __syncthreads();
    if (tid < KK)
        g_costpart[(b*8 + tile)*KK + tid] =
            sred[0][tid] + sred[1][tid] + sred[2][tid] + sred[3][tid];
}

// =========================== Kernel C =======================================
__device__ __forceinline__ float gelu_exact(float x) {
    return 0.5f * x * (1.f + erff(x * 0.70710678118654752440f));
}

__global__ void __launch_bounds__(128)
kC(const float* __restrict__ p2s, const int* __restrict__ band_idx,
   const float* __restrict__ log_temp, const float* __restrict__ band_emb,
   const float* __restrict__ w1, const float* __restrict__ b1,
   const float* __restrict__ w2, const float* __restrict__ b2,
   const float* __restrict__ w3, const float* __restrict__ b3,
   float* __restrict__ out, int stride)
{
    const int b = blockIdx.x, tid = threadIdx.x;
    __shared__ float sfeat[212];
    __shared__ float scost[KK];
    __shared__ float sh1[128], sh2[128], sout3[3];
    __shared__ float sS, scdx, scdy, sconf;

    if (tid == 0) {
        float s = 0.f;
        for (int h = 0; h < NH; h++) s += g_Spart[b*NH + h];
        sS = s;
    }
    if (tid < KK) {
        float c = 0.f;
        for (int t = 0; t < 8; t++) c += g_costpart[(b*8 + t)*KK + tid];
        scost[tid] = c;
    }
    if (tid < 64) {
        float pr = 0.f, pv = 0.f;
        for (int h = 0; h < NH; h++) {
            pr += g_poolr[(b*NH + h)*NC + tid];
            pv += g_poolv[(b*NH + h)*NC + tid];
        }
        sfeat[tid] = pr; sfeat[64 + tid] = pv; sfeat[128 + tid] = pr - pv;
    }
    __syncthreads();

    if (tid == 0) {
        const float temp  = fmaxf(expf(log_temp[0]), 1e-3f);
        const float scale = 1.f / ((sS + 1e-8f) * 8.f * temp);  // sqrt(C)=8
        float l[KK], mx = -1e30f;
        for (int k = 0; k < KK; k++) { l[k] = scost[k] * scale; mx = fmaxf(mx, l[k]); }
        float sum = 0.f;
        for (int k = 0; k < KK; k++) { float p = expf(l[k] - mx); l[k] = p; sum += p; }
        const float inv = 1.f / sum;
        float cdx = 0.f, cdy = 0.f, cf = 0.f;
        for (int k = 0; k < KK; k++) {
            float p = l[k] * inv;
            cf  = fmaxf(cf, p);
            cdx += p * (float)((k % 7) - 3);
            cdy += p * (float)((k / 7) - 3);
        }
        scdx = cdx; scdy = cdy; sconf = cf;
        sfeat[192] = cdx; sfeat[193] = cdy;
    }
    if (tid < 16) sfeat[194 + tid] = band_emb[band_idx[b]*16 + tid];
    __syncthreads();

    float a = b1[tid];
    for (int f = 0; f < 210; f++) a = fmaf(sfeat[f], w1[f*128 + tid], a);
    sh1[tid] = gelu_exact(a);
    __syncthreads();

    a = b2[tid];
    for (int f = 0; f < 128; f++) a = fmaf(sh1[f], w2[f*128 + tid], a);
    sh2[tid] = gelu_exact(a);
    __syncthreads();

    if (tid < 3) {
        float a3 = b3[tid];
        for (int f = 0; f < 128; f++) a3 = fmaf(sh2[f], w3[f*3 + tid], a3);
        sout3[tid] = a3;
    }
    __syncthreads();

    if (tid == 0) {
        const float dx = scdx + sout3[0];
        const float dy = scdy + sout3[1];
        const float ls = fminf(fmaxf(sout3[2], -6.f), 3.f);
        const float s0 = p2s[b*4 + 0]*dx + p2s[b*4 + 1]*dy;
        const float s1 = p2s[b*4 + 2]*dx + p2s[b*4 + 3]*dy;
        float* o = out + (size_t)b * stride;
        if (stride > 0) o[0] = dx;
        if (stride > 1) o[1] = dy;
        if (stride > 2) o[2] = s0;
        if (stride > 3) o[3] = s1;
        if (stride > 4) o[4] = ls;
        if (stride > 5) o[5] = sconf;
        for (int j = 6; j < stride; j++) o[j] = 0.f;
    }
}

// =========================== launch =========================================
extern "C" void kernel_launch(void* const* d_in, const int* in_sizes, int n_in,
                              void* d_out, int out_size)
{
    const float* rubin = (const float*)d_in[0];
    const float* vis   = (const float*)d_in[1];
    const float* p2s   = (const float*)d_in[2];
    const int*   bidx  = (const int*)  d_in[3];
    const float* wr    = (const float*)d_in[4];
    const float* wv    = (const float*)d_in[5];
    const float* lt    = (const float*)d_in[6];
    const float* bemb  = (const float*)d_in[7];
    const float* w1    = (const float*)d_in[8];
    const float* b1    = (const float*)d_in[9];
    const float* w2    = (const float*)d_in[10];
    const float* b2    = (const float*)d_in[11];
    const float* w3    = (const float*)d_in[12];
    const float* b3    = (const float*)d_in[13];
    float* out = (float*)d_out;
    const int stride = out_size / NB;

    // gauss normalizer (separable, H=W=64)
    double Sy = 0.0;
    for (int i = 0; i < 64; i++) {
        double y = -1.0 + 2.0 * (double)i / 63.0;
        Sy += exp(-2.0 * y * y);
    }
    const float inv_gsum = (float)(1.0 / (Sy * Sy));

    const int ka_smem = KA_SMEM_FLOATS * 4;   // 74752 B
    cudaFuncSetAttribute(kA, cudaFuncAttributeMaxDynamicSharedMemorySize, ka_smem);
    const int kb_smem = 4 * 14 * 65 * 16;     // 58240 B
    cudaFuncSetAttribute(kB, cudaFuncAttributeMaxDynamicSharedMemorySize, kb_smem);

    kA<<<dim3(NH, NB), 256, ka_smem>>>(rubin, vis, wr, wv, inv_gsum);
    kB<<<dim3(8, NB), 128, kb_smem>>>();
    kC<<<NB, 128>>>(p2s, bidx, lt, bemb, w1, b1, w2, b2, w3, b3, out, stride);
}

// round 5
// speedup vs baseline: 1.7693x; 1.0881x over previous
#include <cuda_runtime.h>
#include <math.h>

#define NB   128   // batch
#define NC   64    // channels
#define NH   64
#define NW   64
#define NPIX (NH*NW)
#define KK   49

typedef unsigned long long u64;

// ---- packed fp32x2 helpers (sm_100+ PTX; full IEEE fp32 per lane) ----------
__device__ __forceinline__ u64 splat2(float a) {
    u64 r; asm("mov.b64 %0, {%1,%1};" : "=l"(r) : "f"(a)); return r;
}
__device__ __forceinline__ void fma2(u64& d, u64 a, u64 b) {
    asm("fma.rn.f32x2 %0, %1, %2, %0;" : "+l"(d) : "l"(a), "l"(b));
}
__device__ __forceinline__ float2 upk(u64 v) {
    float2 f; asm("mov.b64 {%0,%1}, %2;" : "=f"(f.x), "=f"(f.y) : "l"(v)); return f;
}
#define GETC(v,cc) ((cc)==0?(v).x:(cc)==1?(v).y:(cc)==2?(v).z:(v).w)

// ---------------- scratch (device globals; no allocations allowed) ----------
__device__ __align__(16) float g_rubinw[NB*NPIX*NC];   // rubin_n * swraw, [b][pix][c]
__device__ __align__(16) float g_visn  [NB*NPIX*NC];   // vis_n,           [b][pix][c]
__device__ float g_costpart[NB*8*KK];
__device__ float g_poolr[NB*NH*NC];
__device__ float g_poolv[NB*NH*NC];
__device__ float g_Spart[NB*NH];

// =========================== Kernel A =======================================
// One block per (b, 2-row pair). 256 threads, 8 warps, TENSOR-SPECIALIZED:
// warps 0-3 -> rubin, warps 4-7 -> vis. Each warp owns 16 outputs
// (og = (wid&3)*16); each thread owns 4 pixels (lane+{0,32,64,96}) of its
// tensor -> 32 u64 f32x2 accumulators. Per 4-channel step per warp:
// 4 distinct x LDS.128 + 16 broadcast weight LDS.128 serving 128 fma2.
#define OFF_WR  0
#define OFF_WV  4352
#define OFF_XR  8704
#define OFF_XV  17408
#define OFF_SQR 26112
#define OFF_SQV 26624
#define OFF_PR  27136
#define OFF_PV  27648
#define OFF_GX  28160
#define OFF_FR  28224
#define OFF_SV  28352
#define OFF_SW  28480
#define KA_SMEM_FLOATS 28608

__global__ void __launch_bounds__(256, 2)
kA(const float* __restrict__ rubin, const float* __restrict__ vis,
   const float* __restrict__ wr, const float* __restrict__ wv, float inv_gsum)
{
    extern __shared__ float sm[];
    float* sWr = sm + OFF_WR;    // [c][o], stride 68
    float* sWv = sm + OFF_WV;
    float* sXr = sm + OFF_XR;    // [pix][c], 128 pixels, stride 68
    float* sXv = sm + OFF_XV;
    float* sSQR = sm + OFF_SQR;  // [4][128]
    float* sSQV = sm + OFF_SQV;  // [4][128]
    float* sPr = sm + OFF_PR;    // [2rows][4q][64c]
    float* sPv = sm + OFF_PV;
    float* sGx = sm + OFF_GX;    // [64]
    float* sFr = sm + OFF_FR;    // [128]
    float* sSv = sm + OFF_SV;    // [128]
    float* sSw = sm + OFF_SW;    // [128]

    const int h0 = blockIdx.x * 2, b = blockIdx.y;
    const int tid = threadIdx.x;
    const int wid = tid >> 5, lane = tid & 31;
    const bool isR = (wid < 4);

    // ---- weights -> smem transposed [c][o] (coalesced global read) ----
    for (int idx = tid; idx < 4096; idx += 256) {
        int o = idx >> 6, c = idx & 63;
        sWr[c*68 + o] = wr[idx];
        sWv[c*68 + o] = wv[idx];
    }
    if (tid < 64) {
        float xxg = -1.f + 2.f * (float)tid / 63.f;
        sGx[tid] = expf(-2.f * xxg * xxg);
    }

    // ---- stage x transposed: sX[pix][c], pix = r*64 + w ----
    {
        const int w0 = tid & 63, cq = tid >> 6;
#pragma unroll
        for (int r = 0; r < 2; r++) {
            const size_t rowbase = (size_t)b*NC*NPIX + (size_t)(h0 + r)*64 + w0;
            const int pofs = (r*64 + w0)*68;
#pragma unroll
            for (int it = 0; it < 4; it++) {
                int c0 = cq*4 + it*16;
                float4 vr, vv;
                vr.x = rubin[rowbase + (size_t)(c0+0)*NPIX];
                vr.y = rubin[rowbase + (size_t)(c0+1)*NPIX];
                vr.z = rubin[rowbase + (size_t)(c0+2)*NPIX];
                vr.w = rubin[rowbase + (size_t)(c0+3)*NPIX];
                vv.x = vis  [rowbase + (size_t)(c0+0)*NPIX];
                vv.y = vis  [rowbase + (size_t)(c0+1)*NPIX];
                vv.z = vis  [rowbase + (size_t)(c0+2)*NPIX];
                vv.w = vis  [rowbase + (size_t)(c0+3)*NPIX];
                *(float4*)&sXr[pofs + c0] = vr;
                *(float4*)&sXv[pofs + c0] = vv;
            }
        }
    }
    __syncthreads();

    // ---- f32x2 register-tiled GEMM (one tensor per warp, 4 pixels/thread) --
    const int og = (wid & 3) * 16;
    const float* sX = isR ? sXr : sXv;
    const float* sW = isR ? sWr : sWv;

    u64 acc[4][8];     // [pixel][output-pair]
#pragma unroll
    for (int pp = 0; pp < 4; pp++)
#pragma unroll
        for (int j = 0; j < 8; j++) acc[pp][j] = 0ull;

#pragma unroll 2
    for (int c0 = 0; c0 < 64; c0 += 4) {
        float4 x[4];
#pragma unroll
        for (int pp = 0; pp < 4; pp++)
            x[pp] = *(const float4*)&sX[(lane + 32*pp)*68 + c0];
#pragma unroll
        for (int cc = 0; cc < 4; cc++) {
            const int c = c0 + cc;
            const ulonglong2 wa = *(const ulonglong2*)&sW[c*68 + og];
            const ulonglong2 wb = *(const ulonglong2*)&sW[c*68 + og + 4];
            const ulonglong2 wc = *(const ulonglong2*)&sW[c*68 + og + 8];
            const ulonglong2 wd = *(const ulonglong2*)&sW[c*68 + og + 12];
#pragma unroll
            for (int pp = 0; pp < 4; pp++) {
                const u64 s = splat2(GETC(x[pp], cc));
                fma2(acc[pp][0], wa.x, s); fma2(acc[pp][1], wa.y, s);
                fma2(acc[pp][2], wb.x, s); fma2(acc[pp][3], wb.y, s);
                fma2(acc[pp][4], wc.x, s); fma2(acc[pp][5], wc.y, s);
                fma2(acc[pp][6], wd.x, s); fma2(acc[pp][7], wd.y, s);
            }
        }
    }

    // ---- pool partials over raw x (still resident in sXr/sXv) ----
    {
        const int c = tid & 63, q = tid >> 6;
#pragma unroll
        for (int r = 0; r < 2; r++) {
            float pr = 0.f, pv = 0.f;
#pragma unroll
            for (int w = 0; w < 16; w++) {
                const int wcol = q*16 + w;
                const int px = r*64 + wcol;
                const float gxw = sGx[wcol];
                pr = fmaf(sXr[px*68 + c], gxw, pr);
                pv = fmaf(sXv[px*68 + c], gxw, pv);
            }
            sPr[(r*4 + q)*64 + c] = pr;
            sPv[(r*4 + q)*64 + c] = pv;
        }
    }

    // ---- per-(warp,pixel) square partials over this warp's 16 outputs ----
    {
        float* sSQ = isR ? sSQR : sSQV;
#pragma unroll
        for (int pp = 0; pp < 4; pp++) {
            float sq = 0.f;
#pragma unroll
            for (int j = 0; j < 8; j++) {
                float2 t = upk(acc[pp][j]);
                sq = fmaf(t.x, t.x, fmaf(t.y, t.y, sq));
            }
            sSQ[(wid & 3)*128 + lane + 32*pp] = sq;
        }
    }
    __syncthreads();

    if (tid < 128) {
        const int pix = tid;           // r*64 + col
        const int r = pix >> 6, col = pix & 63;
        float ssr = 0.f, ssv = 0.f;
#pragma unroll
        for (int w = 0; w < 4; w++) { ssr += sSQR[w*128 + pix]; ssv += sSQV[w*128 + pix]; }
        const float sr = 1.f / fmaxf(sqrtf(ssr), 1e-6f);
        const float sv = 1.f / fmaxf(sqrtf(ssv), 1e-6f);
        const float e  = ssr * sr * sr;
        const float yy = -1.f + 2.f * (float)(h0 + r) / 63.f;
        const float gy = expf(-2.f*yy*yy);
        const float g  = gy * sGx[col] * inv_gsum;
        const float swraw = e * g;
        sFr[pix] = sr * swraw;
        sSv[pix] = sv;
        sSw[pix] = swraw;
        // pools: reuse (r, col) as (row, channel)
        const float gyn = gy * inv_gsum;
        const int c = col;
        g_poolr[(b*NH + h0 + r)*NC + c] =
            (sPr[(r*4+0)*64+c] + sPr[(r*4+1)*64+c] + sPr[(r*4+2)*64+c] + sPr[(r*4+3)*64+c]) * gyn;
        g_poolv[(b*NH + h0 + r)*NC + c] =
            (sPv[(r*4+0)*64+c] + sPv[(r*4+1)*64+c] + sPv[(r*4+2)*64+c] + sPv[(r*4+3)*64+c]) * gyn;
    }
    __syncthreads();

    if (tid < 2) {
        float s = 0.f;
        for (int i = 0; i < 64; i++) s += sSw[tid*64 + i];
        g_Spart[b*NH + h0 + tid] = s;
    }

    // ---- scale accums and re-stage into own tensor's sX (raw x now dead) ----
    {
        float* sXo = isR ? sXr : sXv;
#pragma unroll
        for (int pp = 0; pp < 4; pp++) {
            const int pix = lane + 32*pp;
            const float f = isR ? sFr[pix] : sSv[pix];
#pragma unroll
            for (int q = 0; q < 4; q++) {
                float2 ta = upk(acc[pp][2*q]), tb = upk(acc[pp][2*q+1]);
                float4 t; t.x = ta.x*f; t.y = ta.y*f; t.z = tb.x*f; t.w = tb.y*f;
                *(float4*)&sXo[pix*68 + og + 4*q] = t;
            }
        }
    }
    __syncthreads();

    // ---- coalesced global stores (pixel-major [b][pix][c]) ----
    {
        const size_t gbase = ((size_t)(b*NPIX + h0*64)) * NC;
#pragma unroll
        for (int k = 0; k < 8; k++) {
            const int idx = k*256 + tid;      // float4 index 0..2047
            const int pix = idx >> 4;
            const int c4  = (idx & 15) * 4;
            *(float4*)&g_rubinw[gbase + pix*64 + c4] = *(float4*)&sXr[pix*68 + c4];
            *(float4*)&g_visn  [gbase + pix*64 + c4] = *(float4*)&sXv[pix*68 + c4];
        }
    }
}

// =========================== Kernel B =======================================
// Correlation costs with f32x2 over channel pairs. Block = (b, 8-row tile).
// 128 threads; each owns 4 adjacent columns. 49 u64 accumulators.
__global__ void __launch_bounds__(128, 2)
kB()
{
    const int tile = blockIdx.x;            // 0..7
    const int b    = blockIdx.y;
    const int h0   = tile * 8;
    const int tid  = threadIdx.x;
    const int row  = tid & 7;
    const int cg   = tid >> 3;              // 0..15, columns 4cg..4cg+3

    extern __shared__ ulonglong2 sv[];      // [(cc4*14 + r)*65 + col]

    u64 acc2[KK];
#pragma unroll
    for (int k = 0; k < KK; k++) acc2[k] = 0ull;

    for (int c0 = 0; c0 < 64; c0 += 16) {
        __syncthreads();
        for (int idx = tid; idx < 14*64*4; idx += 128) {
            int cc4 = idx & 3, col = (idx >> 2) & 63, r = idx >> 8;
            int gr = min(max(h0 + r - 3, 0), 63);
            sv[(cc4*14 + r)*65 + col] =
                *(const ulonglong2*)(g_visn + ((size_t)(b*NPIX + gr*64 + col))*NC + c0 + cc4*4);
        }
        __syncthreads();

        for (int cc4 = 0; cc4 < 4; cc4++) {
            ulonglong2 rb[4];
#pragma unroll
            for (int p = 0; p < 4; p++)
                rb[p] = *(const ulonglong2*)(g_rubinw +
                        ((size_t)(b*NPIX + (h0 + row)*64 + cg*4 + p))*NC + c0 + cc4*4);
#pragma unroll
            for (int dy = 0; dy < 7; dy++) {
                const ulonglong2* base = &sv[(cc4*14 + row + dy)*65];
                ulonglong2 w[10];
#pragma unroll
                for (int j = 0; j < 10; j++) {
                    int col = min(max(cg*4 + j - 3, 0), 63);
                    w[j] = base[col];
                }
#pragma unroll
                for (int dx = 0; dx < 7; dx++) {
#pragma unroll
                    for (int p = 0; p < 4; p++) {
                        fma2(acc2[dy*7 + dx], rb[p].x, w[p + dx].x);
                        fma2(acc2[dy*7 + dx], rb[p].y, w[p + dx].y);
                    }
                }
            }
        }
    }

    __shared__ float sred[4][KK];
    const int wid = tid >> 5, lane = tid & 31;
#pragma unroll
    for (int k = 0; k < KK; k++) {
        float2 t = upk(acc2[k]);
        float v = t.x + t.y;
#pragma unroll
        for (int off = 16; off > 0; off >>= 1) v += __shfl_down_sync(0xffffffffu, v, off);
        if (lane == 0) sred[wid][k] = v;
    }
    __syncthreads();
    if (tid < KK)
        g_costpart[(b*8 + tile)*KK + tid] =
            sred[0][tid] + sred[1][tid] + sred[2][tid] + sred[3][tid];
}

// =========================== Kernel C =======================================
__device__ __forceinline__ float gelu_exact(float x) {
    return 0.5f * x * (1.f + erff(x * 0.70710678118654752440f));
}

__global__ void __launch_bounds__(128)
kC(const float* __restrict__ p2s, const int* __restrict__ band_idx,
   const float* __restrict__ log_temp, const float* __restrict__ band_emb,
   const float* __restrict__ w1, const float* __restrict__ b1,
   const float* __restrict__ w2, const float* __restrict__ b2,
   const float* __restrict__ w3, const float* __restrict__ b3,
   float* __restrict__ out, int stride)
{
    const int b = blockIdx.x, tid = threadIdx.x;
    __shared__ float sfeat[212];
    __shared__ float scost[KK];
    __shared__ float sh1[128], sh2[128], sout3[3];
    __shared__ float sS, scdx, scdy, sconf;

    if (tid == 0) {
        float s = 0.f;
        for (int h = 0; h < NH; h++) s += g_Spart[b*NH + h];
        sS = s;
    }
    if (tid < KK) {
        float c = 0.f;
        for (int t = 0; t < 8; t++) c += g_costpart[(b*8 + t)*KK + tid];
        scost[tid] = c;
    }
    if (tid < 64) {
        float pr = 0.f, pv = 0.f;
        for (int h = 0; h < NH; h++) {
            pr += g_poolr[(b*NH + h)*NC + tid];
            pv += g_poolv[(b*NH + h)*NC + tid];
        }
        sfeat[tid] = pr; sfeat[64 + tid] = pv; sfeat[128 + tid] = pr - pv;
    }
    __syncthreads();

    if (tid == 0) {
        const float temp  = fmaxf(expf(log_temp[0]), 1e-3f);
        const float scale = 1.f / ((sS + 1e-8f) * 8.f * temp);  // sqrt(C)=8
        float l[KK], mx = -1e30f;
        for (int k = 0; k < KK; k++) { l[k] = scost[k] * scale; mx = fmaxf(mx, l[k]); }
        float sum = 0.f;
        for (int k = 0; k < KK; k++) { float p = expf(l[k] - mx); l[k] = p; sum += p; }
        const float inv = 1.f / sum;
        float cdx = 0.f, cdy = 0.f, cf = 0.f;
        for (int k = 0; k < KK; k++) {
            float p = l[k] * inv;
            cf  = fmaxf(cf, p);
            cdx += p * (float)((k % 7) - 3);
            cdy += p * (float)((k / 7) - 3);
        }
        scdx = cdx; scdy = cdy; sconf = cf;
        sfeat[192] = cdx; sfeat[193] = cdy;
    }
    if (tid < 16) sfeat[194 + tid] = band_emb[band_idx[b]*16 + tid];
    __syncthreads();

    float a = b1[tid];
    for (int f = 0; f < 210; f++) a = fmaf(sfeat[f], w1[f*128 + tid], a);
    sh1[tid] = gelu_exact(a);
    __syncthreads();

    a = b2[tid];
    for (int f = 0; f < 128; f++) a = fmaf(sh1[f], w2[f*128 + tid], a);
    sh2[tid] = gelu_exact(a);
    __syncthreads();

    if (tid < 3) {
        float a3 = b3[tid];
        for (int f = 0; f < 128; f++) a3 = fmaf(sh2[f], w3[f*3 + tid], a3);
        sout3[tid] = a3;
    }
    __syncthreads();

    if (tid == 0) {
        const float dx = scdx + sout3[0];
        const float dy = scdy + sout3[1];
        const float ls = fminf(fmaxf(sout3[2], -6.f), 3.f);
        const float s0 = p2s[b*4 + 0]*dx + p2s[b*4 + 1]*dy;
        const float s1 = p2s[b*4 + 2]*dx + p2s[b*4 + 3]*dy;
        float* o = out + (size_t)b * stride;
        if (stride > 0) o[0] = dx;
        if (stride > 1) o[1] = dy;
        if (stride > 2) o[2] = s0;
        if (stride > 3) o[3] = s1;
        if (stride > 4) o[4] = ls;
        if (stride > 5) o[5] = sconf;
        for (int j = 6; j < stride; j++) o[j] = 0.f;
    }
}

// =========================== launch =========================================
extern "C" void kernel_launch(void* const* d_in, const int* in_sizes, int n_in,
                              void* d_out, int out_size)
{
    const float* rubin = (const float*)d_in[0];
    const float* vis   = (const float*)d_in[1];
    const float* p2s   = (const float*)d_in[2];
    const int*   bidx  = (const int*)  d_in[3];
    const float* wr    = (const float*)d_in[4];
    const float* wv    = (const float*)d_in[5];
    const float* lt    = (const float*)d_in[6];
    const float* bemb  = (const float*)d_in[7];
    const float* w1    = (const float*)d_in[8];
    const float* b1    = (const float*)d_in[9];
    const float* w2    = (const float*)d_in[10];
    const float* b2    = (const float*)d_in[11];
    const float* w3    = (const float*)d_in[12];
    const float* b3    = (const float*)d_in[13];
    float* out = (float*)d_out;
    const int stride = out_size / NB;

    // gauss normalizer (separable, H=W=64)
    double Sy = 0.0;
    for (int i = 0; i < 64; i++) {
        double y = -1.0 + 2.0 * (double)i / 63.0;
        Sy += exp(-2.0 * y * y);
    }
    const float inv_gsum = (float)(1.0 / (Sy * Sy));

    const int ka_smem = KA_SMEM_FLOATS * 4;   // 114432 B
    cudaFuncSetAttribute(kA, cudaFuncAttributeMaxDynamicSharedMemorySize, ka_smem);
    const int kb_smem = 4 * 14 * 65 * 16;     // 58240 B
    cudaFuncSetAttribute(kB, cudaFuncAttributeMaxDynamicSharedMemorySize, kb_smem);

    kA<<<dim3(NH/2, NB), 256, ka_smem>>>(rubin, vis, wr, wv, inv_gsum);
    kB<<<dim3(8, NB), 128, kb_smem>>>();
    kC<<<NB, 128>>>(p2s, bidx, lt, bemb, w1, b1, w2, b2, w3, b3, out, stride);
}

// round 6
// speedup vs baseline: 1.8454x; 1.0431x over previous
#include <cuda_runtime.h>
#include <math.h>

#define NB   128   // batch
#define NC   64    // channels
#define NH   64
#define NW   64
#define NPIX (NH*NW)
#define KK   49

typedef unsigned long long u64;

// ---- packed fp32x2 helpers (sm_100+ PTX; full IEEE fp32 per lane) ----------
__device__ __forceinline__ u64 splat2(float a) {
    u64 r; asm("mov.b64 %0, {%1,%1};" : "=l"(r) : "f"(a)); return r;
}
__device__ __forceinline__ void fma2(u64& d, u64 a, u64 b) {
    asm("fma.rn.f32x2 %0, %1, %2, %0;" : "+l"(d) : "l"(a), "l"(b));
}
__device__ __forceinline__ float2 upk(u64 v) {
    float2 f; asm("mov.b64 {%0,%1}, %2;" : "=f"(f.x), "=f"(f.y) : "l"(v)); return f;
}
#define GETC(v,cc) ((cc)==0?(v).x:(cc)==1?(v).y:(cc)==2?(v).z:(v).w)

// ---------------- scratch (device globals; no allocations allowed) ----------
// Layout: [b][cb=0..3][pix][16ch]  (cb = 16-channel block)
__device__ __align__(16) float g_rubinw[NB*NPIX*NC];
__device__ __align__(16) float g_visn  [NB*NPIX*NC];
__device__ float g_costpart[NB*8*KK];
__device__ float g_poolr[NB*NH*NC];
__device__ float g_poolv[NB*NH*NC];
__device__ float g_Spart[NB*NH];

// =========================== Kernel A =======================================
// One block per (b, 2-row pair). 256 threads, 8 warps, TENSOR-SPECIALIZED:
// warps 0-3 -> rubin, warps 4-7 -> vis. Each warp owns 16 outputs; each
// thread owns 4 pixels -> 32 u64 f32x2 accumulators.
#define OFF_WR  0
#define OFF_WV  4352
#define OFF_XR  8704
#define OFF_XV  17408
#define OFF_SQR 26112
#define OFF_SQV 26624
#define OFF_PR  27136
#define OFF_PV  27648
#define OFF_GX  28160
#define OFF_FR  28224
#define OFF_SV  28352
#define OFF_SW  28480
#define KA_SMEM_FLOATS 28608

__global__ void __launch_bounds__(256, 2)
kA(const float* __restrict__ rubin, const float* __restrict__ vis,
   const float* __restrict__ wr, const float* __restrict__ wv, float inv_gsum)
{
    extern __shared__ float sm[];
    float* sWr = sm + OFF_WR;    // [c][o], stride 68
    float* sWv = sm + OFF_WV;
    float* sXr = sm + OFF_XR;    // [pix][c], 128 pixels, stride 68
    float* sXv = sm + OFF_XV;
    float* sSQR = sm + OFF_SQR;  // [4][128]
    float* sSQV = sm + OFF_SQV;  // [4][128]
    float* sPr = sm + OFF_PR;    // [2rows][4q][64c]
    float* sPv = sm + OFF_PV;
    float* sGx = sm + OFF_GX;    // [64]
    float* sFr = sm + OFF_FR;    // [128]
    float* sSv = sm + OFF_SV;    // [128]
    float* sSw = sm + OFF_SW;    // [128]

    const int h0 = blockIdx.x * 2, b = blockIdx.y;
    const int tid = threadIdx.x;
    const int wid = tid >> 5, lane = tid & 31;
    const bool isR = (wid < 4);

    // ---- weights -> smem transposed [c][o] (coalesced global read) ----
    for (int idx = tid; idx < 4096; idx += 256) {
        int o = idx >> 6, c = idx & 63;
        sWr[c*68 + o] = wr[idx];
        sWv[c*68 + o] = wv[idx];
    }
    if (tid < 64) {
        float xxg = -1.f + 2.f * (float)tid / 63.f;
        sGx[tid] = expf(-2.f * xxg * xxg);
    }

    // ---- stage x transposed: sX[pix][c], pix = r*64 + w ----
    {
        const int w0 = tid & 63, cq = tid >> 6;
#pragma unroll
        for (int r = 0; r < 2; r++) {
            const size_t rowbase = (size_t)b*NC*NPIX + (size_t)(h0 + r)*64 + w0;
            const int pofs = (r*64 + w0)*68;
#pragma unroll
            for (int it = 0; it < 4; it++) {
                int c0 = cq*4 + it*16;
                float4 vr, vv;
                vr.x = rubin[rowbase + (size_t)(c0+0)*NPIX];
                vr.y = rubin[rowbase + (size_t)(c0+1)*NPIX];
                vr.z = rubin[rowbase + (size_t)(c0+2)*NPIX];
                vr.w = rubin[rowbase + (size_t)(c0+3)*NPIX];
                vv.x = vis  [rowbase + (size_t)(c0+0)*NPIX];
                vv.y = vis  [rowbase + (size_t)(c0+1)*NPIX];
                vv.z = vis  [rowbase + (size_t)(c0+2)*NPIX];
                vv.w = vis  [rowbase + (size_t)(c0+3)*NPIX];
                *(float4*)&sXr[pofs + c0] = vr;
                *(float4*)&sXv[pofs + c0] = vv;
            }
        }
    }
    __syncthreads();

    // ---- f32x2 register-tiled GEMM (one tensor per warp, 4 pixels/thread) --
    const int og = (wid & 3) * 16;
    const float* sX = isR ? sXr : sXv;
    const float* sW = isR ? sWr : sWv;

    u64 acc[4][8];     // [pixel][output-pair]
#pragma unroll
    for (int pp = 0; pp < 4; pp++)
#pragma unroll
        for (int j = 0; j < 8; j++) acc[pp][j] = 0ull;

#pragma unroll 2
    for (int c0 = 0; c0 < 64; c0 += 4) {
        float4 x[4];
#pragma unroll
        for (int pp = 0; pp < 4; pp++)
            x[pp] = *(const float4*)&sX[(lane + 32*pp)*68 + c0];
#pragma unroll
        for (int cc = 0; cc < 4; cc++) {
            const int c = c0 + cc;
            const ulonglong2 wa = *(const ulonglong2*)&sW[c*68 + og];
            const ulonglong2 wb = *(const ulonglong2*)&sW[c*68 + og + 4];
            const ulonglong2 wc = *(const ulonglong2*)&sW[c*68 + og + 8];
            const ulonglong2 wd = *(const ulonglong2*)&sW[c*68 + og + 12];
#pragma unroll
            for (int pp = 0; pp < 4; pp++) {
                const u64 s = splat2(GETC(x[pp], cc));
                fma2(acc[pp][0], wa.x, s); fma2(acc[pp][1], wa.y, s);
                fma2(acc[pp][2], wb.x, s); fma2(acc[pp][3], wb.y, s);
                fma2(acc[pp][4], wc.x, s); fma2(acc[pp][5], wc.y, s);
                fma2(acc[pp][6], wd.x, s); fma2(acc[pp][7], wd.y, s);
            }
        }
    }

    // ---- pool partials over raw x (still resident in sXr/sXv) ----
    {
        const int c = tid & 63, q = tid >> 6;
#pragma unroll
        for (int r = 0; r < 2; r++) {
            float pr = 0.f, pv = 0.f;
#pragma unroll
            for (int w = 0; w < 16; w++) {
                const int wcol = q*16 + w;
                const int px = r*64 + wcol;
                const float gxw = sGx[wcol];
                pr = fmaf(sXr[px*68 + c], gxw, pr);
                pv = fmaf(sXv[px*68 + c], gxw, pv);
            }
            sPr[(r*4 + q)*64 + c] = pr;
            sPv[(r*4 + q)*64 + c] = pv;
        }
    }

    // ---- per-(warp,pixel) square partials over this warp's 16 outputs ----
    {
        float* sSQ = isR ? sSQR : sSQV;
#pragma unroll
        for (int pp = 0; pp < 4; pp++) {
            float sq = 0.f;
#pragma unroll
            for (int j = 0; j < 8; j++) {
                float2 t = upk(acc[pp][j]);
                sq = fmaf(t.x, t.x, fmaf(t.y, t.y, sq));
            }
            sSQ[(wid & 3)*128 + lane + 32*pp] = sq;
        }
    }
    __syncthreads();

    if (tid < 128) {
        const int pix = tid;           // r*64 + col
        const int r = pix >> 6, col = pix & 63;
        float ssr = 0.f, ssv = 0.f;
#pragma unroll
        for (int w = 0; w < 4; w++) { ssr += sSQR[w*128 + pix]; ssv += sSQV[w*128 + pix]; }
        const float sr = 1.f / fmaxf(sqrtf(ssr), 1e-6f);
        const float sv = 1.f / fmaxf(sqrtf(ssv), 1e-6f);
        const float e  = ssr * sr * sr;
        const float yy = -1.f + 2.f * (float)(h0 + r) / 63.f;
        const float gy = expf(-2.f*yy*yy);
        const float g  = gy * sGx[col] * inv_gsum;
        const float swraw = e * g;
        sFr[pix] = sr * swraw;
        sSv[pix] = sv;
        sSw[pix] = swraw;
        const float gyn = gy * inv_gsum;
        const int c = col;
        g_poolr[(b*NH + h0 + r)*NC + c] =
            (sPr[(r*4+0)*64+c] + sPr[(r*4+1)*64+c] + sPr[(r*4+2)*64+c] + sPr[(r*4+3)*64+c]) * gyn;
        g_poolv[(b*NH + h0 + r)*NC + c] =
            (sPv[(r*4+0)*64+c] + sPv[(r*4+1)*64+c] + sPv[(r*4+2)*64+c] + sPv[(r*4+3)*64+c]) * gyn;
    }
    __syncthreads();

    if (tid < 2) {
        float s = 0.f;
        for (int i = 0; i < 64; i++) s += sSw[tid*64 + i];
        g_Spart[b*NH + h0 + tid] = s;
    }

    // ---- scale accums and re-stage into own tensor's sX (raw x now dead) ----
    {
        float* sXo = isR ? sXr : sXv;
#pragma unroll
        for (int pp = 0; pp < 4; pp++) {
            const int pix = lane + 32*pp;
            const float f = isR ? sFr[pix] : sSv[pix];
#pragma unroll
            for (int q = 0; q < 4; q++) {
                float2 ta = upk(acc[pp][2*q]), tb = upk(acc[pp][2*q+1]);
                float4 t; t.x = ta.x*f; t.y = ta.y*f; t.z = tb.x*f; t.w = tb.y*f;
                *(float4*)&sXo[pix*68 + og + 4*q] = t;
            }
        }
    }
    __syncthreads();

    // ---- coalesced global stores: layout [b][cb][pix][16] ----
    {
#pragma unroll
        for (int k = 0; k < 8; k++) {
            const int idx = k*256 + tid;      // f4 idx 0..2047
            const int q   = idx & 3;
            const int pix = (idx >> 2) & 127;
            const int cb  = idx >> 9;         // 0..3
            const size_t dst = ((size_t)(b*4 + cb)*NPIX + (size_t)h0*64 + pix)*16 + q*4;
            *(float4*)&g_rubinw[dst] = *(float4*)&sXr[pix*68 + cb*16 + q*4];
            *(float4*)&g_visn  [dst] = *(float4*)&sXv[pix*68 + cb*16 + q*4];
        }
    }
}

// =========================== Kernel B =======================================
// Correlation costs, channel-split threads. Block = (b, 8-row tile).
// 128 threads: q = tid&3 (channel quarter of 16-ch chunk), cp = tid>>2
// (column pair: cols 2cp, 2cp+1). Each thread covers ALL 8 rows.
// smem vis tile: f4 idx = t*384 + col*6 + q  (x6 stride -> conflict-free
// 8-quad spread per LDS.128 phase). 14 window rows (8 + 6 halo).
#define KB_SMEM_BYTES (14*384*16)   // 86016

__global__ void __launch_bounds__(128, 2)
kB()
{
    const int tile = blockIdx.x;            // 0..7
    const int b    = blockIdx.y;
    const int h0   = tile * 8;
    const int tid  = threadIdx.x;
    const int q    = tid & 3;
    const int cp   = tid >> 2;              // 0..31, cols 2cp, 2cp+1

    extern __shared__ float4 sv[];          // [t*384 + col*6 + q]

    u64 acc2[KK];
#pragma unroll
    for (int k = 0; k < KK; k++) acc2[k] = 0ull;

    for (int cb = 0; cb < 4; cb++) {
        const float* vplane = g_visn   + (size_t)(b*4 + cb)*NPIX*16;
        const float* rplane = g_rubinw + (size_t)(b*4 + cb)*NPIX*16;

        __syncthreads();
        // stage 14 window rows x 64 cols x 16 ch, fully coalesced reads
        for (int idx = tid; idx < 14*64*4; idx += 128) {
            const int q4  = idx & 3;
            const int col = (idx >> 2) & 63;
            const int t   = idx >> 8;
            const int gr  = min(max(h0 + t - 3, 0), 63);
            sv[t*384 + col*6 + q4] =
                *(const float4*)(vplane + ((size_t)(gr*64 + col))*16 + q4*4);
        }
        __syncthreads();

        // rubin registers: 8 rows x 2 cols x 4 ch (this thread's quarter)
        ulonglong2 rb2[8][2];
#pragma unroll
        for (int r = 0; r < 8; r++)
#pragma unroll
            for (int cc = 0; cc < 2; cc++)
                rb2[r][cc] = *(const ulonglong2*)(rplane +
                    ((size_t)((h0 + r)*64 + 2*cp + cc))*16 + q*4);

        // window loop: t = local window row (global h0 + t - 3)
#pragma unroll
        for (int t = 0; t < 14; t++) {
            ulonglong2 w2[8];
#pragma unroll
            for (int j = 0; j < 8; j++) {
                const int colw = min(max(2*cp + j - 3, 0), 63);
                w2[j] = *(const ulonglong2*)&sv[t*384 + colw*6 + q];
            }
#pragma unroll
            for (int k = 0; k < 7; k++) {
                const int r = t - k;
                if (r >= 0 && r <= 7) {
#pragma unroll
                    for (int dx = 0; dx < 7; dx++) {
                        fma2(acc2[k*7 + dx], rb2[r][0].x, w2[dx].x);
                        fma2(acc2[k*7 + dx], rb2[r][0].y, w2[dx].y);
                        fma2(acc2[k*7 + dx], rb2[r][1].x, w2[dx+1].x);
                        fma2(acc2[k*7 + dx], rb2[r][1].y, w2[dx+1].y);
                    }
                }
            }
        }
    }

    __shared__ float sred[4][KK];
    const int wid = tid >> 5, lane = tid & 31;
#pragma unroll
    for (int k = 0; k < KK; k++) {
        float2 t = upk(acc2[k]);
        float v = t.x + t.y;
#pragma unroll
        for (int off = 16; off > 0; off >>= 1) v += __shfl_down_sync(0xffffffffu, v, off);
        if (lane == 0) sred[wid][k] = v;
    }
    __syncthreads();
    if (tid < KK)
        g_costpart[(b*8 + tile)*KK + tid] =
            sred[0][tid] + sred[1][tid] + sred[2][tid] + sred[3][tid];
}

// =========================== Kernel C =======================================
__device__ __forceinline__ float gelu_exact(float x) {
    return 0.5f * x * (1.f + erff(x * 0.70710678118654752440f));
}

__global__ void __launch_bounds__(128)
kC(const float* __restrict__ p2s, const int* __restrict__ band_idx,
   const float* __restrict__ log_temp, const float* __restrict__ band_emb,
   const float* __restrict__ w1, const float* __restrict__ b1,
   const float* __restrict__ w2, const float* __restrict__ b2,
   const float* __restrict__ w3, const float* __restrict__ b3,
   float* __restrict__ out, int stride)
{
    const int b = blockIdx.x, tid = threadIdx.x;
    __shared__ float sfeat[212];
    __shared__ float scost[KK];
    __shared__ float sh1[128], sh2[128], sout3[3];
    __shared__ float sS, scdx, scdy, sconf;

    if (tid == 0) {
        float s = 0.f;
        for (int h = 0; h < NH; h++) s += g_Spart[b*NH + h];
        sS = s;
    }
    if (tid < KK) {
        float c = 0.f;
        for (int t = 0; t < 8; t++) c += g_costpart[(b*8 + t)*KK + tid];
        scost[tid] = c;
    }
    if (tid < 64) {
        float pr = 0.f, pv = 0.f;
        for (int h = 0; h < NH; h++) {
            pr += g_poolr[(b*NH + h)*NC + tid];
            pv += g_poolv[(b*NH + h)*NC + tid];
        }
        sfeat[tid] = pr; sfeat[64 + tid] = pv; sfeat[128 + tid] = pr - pv;
    }
    __syncthreads();

    if (tid == 0) {
        const float temp  = fmaxf(expf(log_temp[0]), 1e-3f);
        const float scale = 1.f / ((sS + 1e-8f) * 8.f * temp);  // sqrt(C)=8
        float l[KK], mx = -1e30f;
        for (int k = 0; k < KK; k++) { l[k] = scost[k] * scale; mx = fmaxf(mx, l[k]); }
        float sum = 0.f;
        for (int k = 0; k < KK; k++) { float p = expf(l[k] - mx); l[k] = p; sum += p; }
        const float inv = 1.f / sum;
        float cdx = 0.f, cdy = 0.f, cf = 0.f;
        for (int k = 0; k < KK; k++) {
            float p = l[k] * inv;
            cf  = fmaxf(cf, p);
            cdx += p * (float)((k % 7) - 3);
            cdy += p * (float)((k / 7) - 3);
        }
        scdx = cdx; scdy = cdy; sconf = cf;
        sfeat[192] = cdx; sfeat[193] = cdy;
    }
    if (tid < 16) sfeat[194 + tid] = band_emb[band_idx[b]*16 + tid];
    __syncthreads();

    float a = b1[tid];
    for (int f = 0; f < 210; f++) a = fmaf(sfeat[f], w1[f*128 + tid], a);
    sh1[tid] = gelu_exact(a);
    __syncthreads();

    a = b2[tid];
    for (int f = 0; f < 128; f++) a = fmaf(sh1[f], w2[f*128 + tid], a);
    sh2[tid] = gelu_exact(a);
    __syncthreads();

    if (tid < 3) {
        float a3 = b3[tid];
        for (int f = 0; f < 128; f++) a3 = fmaf(sh2[f], w3[f*3 + tid], a3);
        sout3[tid] = a3;
    }
    __syncthreads();

    if (tid == 0) {
        const float dx = scdx + sout3[0];
        const float dy = scdy + sout3[1];
        const float ls = fminf(fmaxf(sout3[2], -6.f), 3.f);
        const float s0 = p2s[b*4 + 0]*dx + p2s[b*4 + 1]*dy;
        const float s1 = p2s[b*4 + 2]*dx + p2s[b*4 + 3]*dy;
        float* o = out + (size_t)b * stride;
        if (stride > 0) o[0] = dx;
        if (stride > 1) o[1] = dy;
        if (stride > 2) o[2] = s0;
        if (stride > 3) o[3] = s1;
        if (stride > 4) o[4] = ls;
        if (stride > 5) o[5] = sconf;
        for (int j = 6; j < stride; j++) o[j] = 0.f;
    }
}

// =========================== launch =========================================
extern "C" void kernel_launch(void* const* d_in, const int* in_sizes, int n_in,
                              void* d_out, int out_size)
{
    const float* rubin = (const float*)d_in[0];
    const float* vis   = (const float*)d_in[1];
    const float* p2s   = (const float*)d_in[2];
    const int*   bidx  = (const int*)  d_in[3];
    const float* wr    = (const float*)d_in[4];
    const float* wv    = (const float*)d_in[5];
    const float* lt    = (const float*)d_in[6];
    const float* bemb  = (const float*)d_in[7];
    const float* w1    = (const float*)d_in[8];
    const float* b1    = (const float*)d_in[9];
    const float* w2    = (const float*)d_in[10];
    const float* b2    = (const float*)d_in[11];
    const float* w3    = (const float*)d_in[12];
    const float* b3    = (const float*)d_in[13];
    float* out = (float*)d_out;
    const int stride = out_size / NB;

    // gauss normalizer (separable, H=W=64)
    double Sy = 0.0;
    for (int i = 0; i < 64; i++) {
        double y = -1.0 + 2.0 * (double)i / 63.0;
        Sy += exp(-2.0 * y * y);
    }
    const float inv_gsum = (float)(1.0 / (Sy * Sy));

    const int ka_smem = KA_SMEM_FLOATS * 4;   // 114432 B
    cudaFuncSetAttribute(kA, cudaFuncAttributeMaxDynamicSharedMemorySize, ka_smem);
    cudaFuncSetAttribute(kB, cudaFuncAttributeMaxDynamicSharedMemorySize, KB_SMEM_BYTES);

    kA<<<dim3(NH/2, NB), 256, ka_smem>>>(rubin, vis, wr, wv, inv_gsum);
    kB<<<dim3(8, NB), 128, KB_SMEM_BYTES>>>();
    kC<<<NB, 128>>>(p2s, bidx, lt, bemb, w1, b1, w2, b2, w3, b3, out, stride);
}